// round 15
// baseline (speedup 1.0000x reference)
#include <cuda_runtime.h>
#include <cuda_bf16.h>
#include <cstdint>

#define NN 50000
#define EE 400000
#define ALPHA 0.2f
#define EPSV 1e-5f
#define NB_SCAN 49   // ceil(50000/1024)

// ---------------- scratch (device globals; no allocations allowed) ----------
__device__ float g_ft[(size_t)NN * 256];   // node projection [N,H,D]
__device__ float g_a1[NN * 8];
__device__ float g_a2[NN * 8];
__device__ float g_w [(size_t)EE * 8];     // exp(attn logits), CSR order [E,H]
__device__ float g_pq[(size_t)NN * 128];   // P|Q per node
__device__ float g_pqw[256 * 128];         // repacked eu_node_w
__device__ float g_fla[256 * 16];          // folded attn weights
__device__ int   g_counts[NN];
__device__ int   g_cursor[NN];
__device__ int   g_incl[NB_SCAN * 1024];
__device__ int   g_off[NN];
__device__ int   g_bsums[NB_SCAN];
__device__ int   g_srcc[EE];               // src[e] in CSR order
__device__ int   g_epos[EE];               // edge -> CSR position
__device__ float g_nstat[512];             // sum | sumsq (256 channels)
__device__ float g_nscale[512];            // scale | bias
__device__ float g_estat[128];             // sum | sumsq (64 channels)
__device__ float g_escale[128];
// bf16 split operands for tensor-core GEMMs
__device__ __nv_bfloat16 g_ah[(size_t)NN * 256];   // A hi, row-major [M,256]
__device__ __nv_bfloat16 g_al[(size_t)NN * 256];   // A lo
__device__ __nv_bfloat16 g_bh[256 * 256];          // B hi (fc_w)
__device__ __nv_bfloat16 g_bl[256 * 256];          // B lo (fc_w)
__device__ __nv_bfloat16 g_bh2[256 * 128];         // B hi (pqw) - separate buffers
__device__ __nv_bfloat16 g_bl2[256 * 128];         // B lo (pqw)

__device__ __forceinline__ float lrelu(float x) { return x > 0.f ? x : ALPHA * x; }

// ---------------- packed fp32x2 helpers --------------------------------------
typedef unsigned long long u64t;

#define FMA2(d, a, b) asm("fma.rn.f32x2 %0, %1, %2, %0;" : "+l"(d) : "l"(a), "l"(b))

__device__ __forceinline__ u64t fdup(float x) {
    u64t v; asm("mov.b64 %0, {%1, %1};" : "=l"(v) : "f"(x)); return v;
}
__device__ __forceinline__ u64t f2u(float x, float y) {
    u64t v; asm("mov.b64 %0, {%1, %2};" : "=l"(v) : "f"(x), "f"(y)); return v;
}
__device__ __forceinline__ float2 u2f(u64t v) {
    float2 f; asm("mov.b64 {%0, %1}, %2;" : "=f"(f.x), "=f"(f.y) : "l"(v)); return f;
}

// ---------------- mma.sync / ldmatrix / cp.async helpers ---------------------
__device__ __forceinline__ uint32_t smem_u32(const void* p) {
    uint32_t a;
    asm("{ .reg .u64 t; cvta.to.shared.u64 t, %1; cvt.u32.u64 %0, t; }" : "=r"(a) : "l"(p));
    return a;
}
__device__ __forceinline__ void ldsm4(uint32_t* r, uint32_t a) {
    asm volatile("ldmatrix.sync.aligned.m8n8.x4.shared.b16 {%0,%1,%2,%3}, [%4];"
        : "=r"(r[0]), "=r"(r[1]), "=r"(r[2]), "=r"(r[3]) : "r"(a));
}
__device__ __forceinline__ void ldsm4t(uint32_t* r, uint32_t a) {
    asm volatile("ldmatrix.sync.aligned.m8n8.x4.trans.shared.b16 {%0,%1,%2,%3}, [%4];"
        : "=r"(r[0]), "=r"(r[1]), "=r"(r[2]), "=r"(r[3]) : "r"(a));
}
__device__ __forceinline__ void mma_bf16(float* c, const uint32_t* a, const uint32_t* b) {
    asm volatile(
        "mma.sync.aligned.m16n8k16.row.col.f32.bf16.bf16.f32 "
        "{%0,%1,%2,%3}, {%4,%5,%6,%7}, {%8,%9}, {%0,%1,%2,%3};"
        : "+f"(c[0]), "+f"(c[1]), "+f"(c[2]), "+f"(c[3])
        : "r"(a[0]), "r"(a[1]), "r"(a[2]), "r"(a[3]), "r"(b[0]), "r"(b[1]));
}
#define CPASYNC(dst, src) \
    asm volatile("cp.async.ca.shared.global [%0], [%1], 16;" :: "r"(dst), "l"(src))
#define CPCOMMIT() asm volatile("cp.async.commit_group;" ::: "memory")

__device__ __forceinline__ uint32_t f2bf2(float x, float y) {
    __nv_bfloat162 b; b.x = __float2bfloat16(x); b.y = __float2bfloat16(y);
    uint32_t u; memcpy(&u, &b, 4); return u;
}
__device__ __forceinline__ float2 bf2f(uint32_t u) {
    __nv_bfloat162 b; memcpy(&b, &u, 4);
    return make_float2(__bfloat162float(b.x), __bfloat162float(b.y));
}

// ---------------- zero per-launch state -------------------------------------
__global__ void zero_all_k() {
    int i = blockIdx.x * blockDim.x + threadIdx.x;
    if (i < NN) { g_counts[i] = 0; g_cursor[i] = 0; }
    if (i < 512) g_nstat[i] = 0.f;
    if (i < 128) g_estat[i] = 0.f;
}

// ---------------- repack eu_node_w [512,64] -> [256,128] (P|Q) --------------
__global__ void build_pqw_k(const float* __restrict__ W) {
    int i = blockIdx.x * blockDim.x + threadIdx.x;
    if (i >= 256 * 128) return;
    int k = i >> 7, j = i & 127;
    g_pqw[i] = (j < 64) ? W[(k << 6) + j] : W[((256 + k) << 6) + (j - 64)];
}

// ---------------- fold attn vectors through fc_w: fla[k][o] ------------------
__global__ void build_fla_k(const float* __restrict__ fc_w, const float* __restrict__ al,
                            const float* __restrict__ ar) {
    int idx = blockIdx.x * blockDim.x + threadIdx.x;
    if (idx >= 4096) return;
    int k = idx >> 4, o = idx & 15;
    const float* w = fc_w + k * 256;
    const float* v = (o < 8) ? (al + (o << 5)) : (ar + ((o - 8) << 5));
    const float* wb = w + ((o & 7) << 5);
    float s = 0.f;
#pragma unroll
    for (int d = 0; d < 32; d++) s = fmaf(wb[d], v[d], s);
    g_fla[k * 16 + o] = s;
}

// ---------------- fused: node_in bf16 hi/lo split + a1,a2 dots ---------------
__global__ void conv_attn_k(const float* __restrict__ X) {
    __shared__ float sFla[256 * 17];
    for (int i = threadIdx.x; i < 4096; i += 256) {
        int k = i >> 4, o = i & 15;
        sFla[k * 17 + o] = g_fla[i];
    }
    __syncthreads();
    int n = blockIdx.x * 8 + (threadIdx.x >> 5);
    if (n >= NN) return;
    int lane = threadIdx.x & 31;
    const float* xr = X + (size_t)n * 256 + lane * 8;
    float4 v0 = *(const float4*)xr;
    float4 v1 = *(const float4*)(xr + 4);
    float xv[8] = {v0.x, v0.y, v0.z, v0.w, v1.x, v1.y, v1.z, v1.w};

    __nv_bfloat162* ahp = (__nv_bfloat162*)g_ah + (size_t)n * 128 + lane * 4;
    __nv_bfloat162* alp = (__nv_bfloat162*)g_al + (size_t)n * 128 + lane * 4;
#pragma unroll
    for (int j = 0; j < 4; j++) {
        float a = xv[2 * j], b = xv[2 * j + 1];
        __nv_bfloat162 hp; hp.x = __float2bfloat16(a); hp.y = __float2bfloat16(b);
        __nv_bfloat162 lp;
        lp.x = __float2bfloat16(a - __bfloat162float(hp.x));
        lp.y = __float2bfloat16(b - __bfloat162float(hp.y));
        ahp[j] = hp; alp[j] = lp;
    }

    float acc[16];
#pragma unroll
    for (int o = 0; o < 16; o++) acc[o] = 0.f;
#pragma unroll
    for (int j = 0; j < 8; j++) {
        const float* f = &sFla[(lane * 8 + j) * 17];
        float x = xv[j];
#pragma unroll
        for (int o = 0; o < 16; o++) acc[o] = fmaf(x, f[o], acc[o]);
    }
#pragma unroll
    for (int off = 16; off; off >>= 1)
#pragma unroll
        for (int o = 0; o < 16; o++) acc[o] += __shfl_xor_sync(0xffffffffu, acc[o], off);
    if (lane < 8)       g_a1[n * 8 + lane] = acc[lane];
    else if (lane < 16) g_a2[n * 8 + (lane - 8)] = acc[lane];
}

// fused: BN-node apply (in place) + bf16 hi/lo split
__global__ void conv_abn_k(float* __restrict__ X) {
    int i = blockIdx.x * blockDim.x + threadIdx.x;
    if (i >= NN * 128) return;
    float2 v = ((float2*)X)[i];
    int c = (i << 1) & 255;
    v.x = fmaf(v.x, g_nscale[c],     g_nscale[256 + c]);
    v.y = fmaf(v.y, g_nscale[c + 1], g_nscale[256 + c + 1]);
    ((float2*)X)[i] = v;
    __nv_bfloat16 h0 = __float2bfloat16(v.x);
    __nv_bfloat16 h1 = __float2bfloat16(v.y);
    __nv_bfloat162 hp; hp.x = h0; hp.y = h1;
    __nv_bfloat162 lp;
    lp.x = __float2bfloat16(v.x - __bfloat162float(h0));
    lp.y = __float2bfloat16(v.y - __bfloat162float(h1));
    ((__nv_bfloat162*)g_ah)[i] = hp;
    ((__nv_bfloat162*)g_al)[i] = lp;
}

// W [K,N] fp32 -> bh/bl (parameterized destination)
__global__ void conv_b_k(const float* __restrict__ W, __nv_bfloat16* __restrict__ BH,
                         __nv_bfloat16* __restrict__ BL, int total) {
    int i = blockIdx.x * blockDim.x + threadIdx.x;
    if (i >= total) return;
    float v = W[i];
    __nv_bfloat16 h = __float2bfloat16(v);
    BH[i] = h;
    BL[i] = __float2bfloat16(v - __bfloat162float(h));
}

// ---------------- tensor-core GEMM via mma.sync (bf16 3-term split) ----------
__global__ __launch_bounds__(256, 2) void gemm_mma_k(
    const __nv_bfloat16* __restrict__ Ah, const __nv_bfloat16* __restrict__ Al,
    const __nv_bfloat16* __restrict__ Bh, const __nv_bfloat16* __restrict__ Bl,
    float* __restrict__ C, int M, int Nsz) {
    extern __shared__ char smem[];
    const int tid = threadIdx.x, lane = tid & 31, w = tid >> 5;
    const int wm = w >> 1, wn = w & 1;
    const int row0 = blockIdx.y * 128, col0 = blockIdx.x * 128;
    const uint32_t sb = smem_u32(smem);
    const int BUF = 37888;

    float acc[2][8][4];
#pragma unroll
    for (int i = 0; i < 2; i++)
#pragma unroll
        for (int j = 0; j < 8; j++)
#pragma unroll
            for (int q = 0; q < 4; q++) acc[i][j][q] = 0.f;

    uint32_t a_base[2][2], b_base[2][4];
    {
        int rl = lane & 15, ch = (lane >> 4) << 4;
#pragma unroll
        for (int t = 0; t < 2; t++)
#pragma unroll
            for (int mf = 0; mf < 2; mf++)
                a_base[t][mf] = t * 10240 + (wm * 32 + mf * 16 + rl) * 80 + ch;
#pragma unroll
        for (int t = 0; t < 2; t++)
#pragma unroll
            for (int p = 0; p < 4; p++)
                b_base[t][p] = 20480 + t * 8704 + rl * 272 + wn * 128 + p * 32 + ch;
    }

    auto stage = [&](int kc, int bb) {
        uint32_t dbase = sb + bb * BUF;
#pragma unroll
        for (int i = 0; i < 4; i++) {
            int idx = tid + i * 256;
            int t = idx >> 9, c = idx & 511;
            int r = c >> 2, kch = c & 3;
            int gr = row0 + r; if (gr >= M) gr = M - 1;
            const char* src = (const char*)(t ? Al : Ah)
                            + ((size_t)gr * 256 + kc * 32 + kch * 8) * 2;
            CPASYNC(dbase + t * 10240 + r * 80 + kch * 16, src);
        }
#pragma unroll
        for (int i = 0; i < 4; i++) {
            int idx = tid + i * 256;
            int t = idx >> 9, c = idx & 511;
            int kr = c >> 4, nch = c & 15;
            const char* src = (const char*)(t ? Bl : Bh)
                            + ((size_t)(kc * 32 + kr) * Nsz + col0 + nch * 8) * 2;
            CPASYNC(dbase + 20480 + t * 8704 + kr * 272 + nch * 16, src);
        }
        CPCOMMIT();
    };

    const int NK = 8;
    stage(0, 0);
    stage(1, 1);

    for (int kc = 0; kc < NK; kc++) {
        int bb = kc & 1;
        if (kc == NK - 1) asm volatile("cp.async.wait_group 0;" ::: "memory");
        else              asm volatile("cp.async.wait_group 1;" ::: "memory");
        __syncthreads();
        uint32_t base = sb + bb * BUF;
#pragma unroll
        for (int ks = 0; ks < 2; ks++) {
            uint32_t ah[2][4], al_[2][4];
            ldsm4(ah[0],  base + a_base[0][0] + ks * 32);
            ldsm4(ah[1],  base + a_base[0][1] + ks * 32);
            ldsm4(al_[0], base + a_base[1][0] + ks * 32);
            ldsm4(al_[1], base + a_base[1][1] + ks * 32);
#pragma unroll
            for (int p = 0; p < 4; p++) {
                uint32_t bh[4], bl_[4];
                ldsm4t(bh,  base + b_base[0][p] + ks * 4352);
                ldsm4t(bl_, base + b_base[1][p] + ks * 4352);
#pragma unroll
                for (int mf = 0; mf < 2; mf++) {
                    mma_bf16(acc[mf][2 * p],     ah[mf],  bh);
                    mma_bf16(acc[mf][2 * p],     al_[mf], bh);
                    mma_bf16(acc[mf][2 * p],     ah[mf],  bl_);
                    mma_bf16(acc[mf][2 * p + 1], ah[mf],  bh + 2);
                    mma_bf16(acc[mf][2 * p + 1], al_[mf], bh + 2);
                    mma_bf16(acc[mf][2 * p + 1], ah[mf],  bl_ + 2);
                }
            }
        }
        __syncthreads();
        if (kc + 2 < NK) stage(kc + 2, bb);
    }

    const int cc = col0 + wn * 64 + (lane & 3) * 2;
#pragma unroll
    for (int mf = 0; mf < 2; mf++) {
        int ra = row0 + wm * 32 + mf * 16 + (lane >> 2);
        int rb = ra + 8;
#pragma unroll
        for (int nf = 0; nf < 8; nf++) {
            int col = cc + nf * 8;
            if (ra < M) *(float2*)(C + (size_t)ra * Nsz + col)
                          = make_float2(acc[mf][nf][0], acc[mf][nf][1]);
            if (rb < M) *(float2*)(C + (size_t)rb * Nsz + col)
                          = make_float2(acc[mf][nf][2], acc[mf][nf][3]);
        }
    }
}

// ---------------- CSR build ---------------------------------------------------
__global__ void count_edges_k(const int* __restrict__ dst) {
    int e = blockIdx.x * blockDim.x + threadIdx.x;
    if (e < EE) atomicAdd(&g_counts[dst[e]], 1);
}

__global__ void scan_block_k() {
    __shared__ int sh[1024];
    int i = blockIdx.x * 1024 + threadIdx.x;
    int v = (i < NN) ? g_counts[i] : 0;
    sh[threadIdx.x] = v;
    __syncthreads();
    for (int off = 1; off < 1024; off <<= 1) {
        int t = (threadIdx.x >= off) ? sh[threadIdx.x - off] : 0;
        __syncthreads();
        sh[threadIdx.x] += t;
        __syncthreads();
    }
    g_incl[i] = sh[threadIdx.x];
    if (threadIdx.x == 1023) g_bsums[blockIdx.x] = sh[1023];
}

__global__ void finish_scan2_k() {
    __shared__ int sh[64];
    int tid = threadIdx.x;
    if (tid < 64)
        sh[tid] = (tid < NB_SCAN && tid < (int)blockIdx.x) ? g_bsums[tid] : 0;
    __syncthreads();
    if (tid < 32) {
        int v = sh[tid] + sh[tid + 32];
#pragma unroll
        for (int off = 16; off; off >>= 1) v += __shfl_down_sync(0xffffffffu, v, off);
        if (tid == 0) sh[0] = v;
    }
    __syncthreads();
    int base = sh[0];
    int i = blockIdx.x * 1024 + tid;
    if (i < NN) g_off[i] = g_incl[i] - g_counts[i] + base;
}

__global__ void scatter_k(const int* __restrict__ src, const int* __restrict__ dst) {
    int e = blockIdx.x * blockDim.x + threadIdx.x;
    if (e < EE) {
        int d = dst[e];
        int p = atomicAdd(&g_cursor[d], 1);
        int pos = g_off[d] + p;
        g_srcc[pos] = src[e];
        g_epos[e] = pos;
    }
}

// ---------------- edge attention MLP as block-tiled FMA2 GEMM ----------------
#define EIP2 68
__global__ void edge_attn2_k(const float* __restrict__ EI, const float* __restrict__ w1,
                             const float* __restrict__ b1, const float* __restrict__ w2,
                             const float* __restrict__ b2, const int* __restrict__ src,
                             const int* __restrict__ dst) {
    __shared__ float sW1[64 * 32];
    __shared__ float sW2[32 * 8];
    __shared__ float sB1[32];
    __shared__ float sB2[8];
    __shared__ float sEI[128 * EIP2];
    __shared__ float sH[128 * 36];
    for (int i = threadIdx.x; i < 2048; i += 256) sW1[i] = w1[i];
    if (threadIdx.x < 256) sW2[threadIdx.x] = w2[threadIdx.x];
    if (threadIdx.x < 32)  sB1[threadIdx.x] = b1[threadIdx.x];
    if (threadIdx.x < 8)   sB2[threadIdx.x] = b2[threadIdx.x];

    const int cg = threadIdx.x & 7;
    const int er = threadIdx.x >> 3;
    const int c0 = cg << 2;
    const int eb = er << 2;

    for (int e0 = blockIdx.x * 128; e0 < EE; e0 += gridDim.x * 128) {
        __syncthreads();
        for (int idx = threadIdx.x; idx < 128 * 16; idx += 256) {
            int e = idx >> 4, c4 = (idx & 15) << 2;
            *(float4*)&sEI[e * EIP2 + c4] = *(const float4*)(EI + (size_t)(e0 + e) * 64 + c4);
        }
        __syncthreads();

        u64t acc[4][2];
        u64t bA = f2u(sB1[c0], sB1[c0 + 1]);
        u64t bB = f2u(sB1[c0 + 2], sB1[c0 + 3]);
#pragma unroll
        for (int i = 0; i < 4; i++) { acc[i][0] = bA; acc[i][1] = bB; }
#pragma unroll 8
        for (int k = 0; k < 64; k++) {
            u64t w01 = *(const u64t*)&sW1[(k << 5) + c0];
            u64t w23 = *(const u64t*)&sW1[(k << 5) + c0 + 2];
#pragma unroll
            for (int i = 0; i < 4; i++) {
                u64t av = fdup(sEI[(eb + i) * EIP2 + k]);
                FMA2(acc[i][0], av, w01);
                FMA2(acc[i][1], av, w23);
            }
        }
#pragma unroll
        for (int i = 0; i < 4; i++) {
            float2 f0 = u2f(acc[i][0]), f1 = u2f(acc[i][1]);
            float* hp = &sH[(eb + i) * 36 + c0];
            hp[0] = lrelu(f0.x); hp[1] = lrelu(f0.y);
            hp[2] = lrelu(f1.x); hp[3] = lrelu(f1.y);
        }
        __syncthreads();

#pragma unroll
        for (int i = 0; i < 4; i++) {
            int e = e0 + eb + i;
            float o = sB2[cg];
#pragma unroll 8
            for (int k = 0; k < 32; k++)
                o = fmaf(sH[(eb + i) * 36 + k], sW2[(k << 3) + cg], o);
            int sN = src[e], dN = dst[e];
            float v = lrelu(o + g_a1[sN * 8 + cg] + g_a2[dN * 8 + cg]);
            g_w[(size_t)g_epos[e] * 8 + cg] = expf(v);
        }
    }
}

// ---------------- per-node aggregation (8-wide main + 4-wide predicated tail) -
__global__ void node_agg_k(const float* __restrict__ xin, float* __restrict__ xout) {
    const int t = threadIdx.x & 63;
    const int head = t >> 3;
    const int g = threadIdx.x >> 6;
    const int ch = t << 2;
    float ls0 = 0, ls1 = 0, ls2 = 0, ls3 = 0, lq0 = 0, lq1 = 0, lq2 = 0, lq3 = 0;
    for (int n = blockIdx.x * 4 + g; n < NN; n += gridDim.x * 4) {
        float a0 = 0, a1 = 0, a2 = 0, a3 = 0, zl = 0;
        int j = g_off[n];
        int j1 = j + g_counts[n];
        while (j + 8 <= j1) {
            int s[8]; float wv[8]; float4 v[8];
#pragma unroll
            for (int u = 0; u < 8; u++) {
                s[u]  = g_srcc[j + u];
                wv[u] = g_w[(size_t)(j + u) * 8 + head];
            }
#pragma unroll
            for (int u = 0; u < 8; u++)
                v[u] = *(const float4*)(g_ft + (size_t)s[u] * 256 + ch);
#pragma unroll
            for (int u = 0; u < 8; u++) {
                a0 = fmaf(v[u].x, wv[u], a0); a1 = fmaf(v[u].y, wv[u], a1);
                a2 = fmaf(v[u].z, wv[u], a2); a3 = fmaf(v[u].w, wv[u], a3);
            }
            if ((t & 7) == 0)
                zl += wv[0] + wv[1] + wv[2] + wv[3] + wv[4] + wv[5] + wv[6] + wv[7];
            j += 8;
        }
        // predicated 4-wide tail (remainder <= 7): clamp index, zero weight
        while (j < j1) {
            int s[4]; float wv[4]; float4 v[4];
#pragma unroll
            for (int u = 0; u < 4; u++) {
                int jj = j + u;
                int jc = jj < j1 ? jj : j1 - 1;
                s[u]  = g_srcc[jc];
                wv[u] = (jj < j1) ? g_w[(size_t)jc * 8 + head] : 0.f;
            }
#pragma unroll
            for (int u = 0; u < 4; u++)
                v[u] = *(const float4*)(g_ft + (size_t)s[u] * 256 + ch);
#pragma unroll
            for (int u = 0; u < 4; u++) {
                a0 = fmaf(v[u].x, wv[u], a0); a1 = fmaf(v[u].y, wv[u], a1);
                a2 = fmaf(v[u].z, wv[u], a2); a3 = fmaf(v[u].w, wv[u], a3);
            }
            if ((t & 7) == 0) zl += wv[0] + wv[1] + wv[2] + wv[3];
            j += 4;
        }
        float z = __shfl_sync(0xffffffffu, zl, (threadIdx.x & 31) & 24);
        if (z == 0.f) z = 1.f;
        float inv = 1.f / z;
        const float4 xi = *(const float4*)(xin + (size_t)n * 256 + ch);
        float x0 = lrelu(fmaf(a0, inv, xi.x));
        float x1 = lrelu(fmaf(a1, inv, xi.y));
        float x2 = lrelu(fmaf(a2, inv, xi.z));
        float x3 = lrelu(fmaf(a3, inv, xi.w));
        *(float4*)(xout + (size_t)n * 256 + ch) = make_float4(x0, x1, x2, x3);
        ls0 += x0; ls1 += x1; ls2 += x2; ls3 += x3;
        lq0 += x0 * x0; lq1 += x1 * x1; lq2 += x2 * x2; lq3 += x3 * x3;
    }
    atomicAdd(&g_nstat[ch + 0], ls0); atomicAdd(&g_nstat[ch + 1], ls1);
    atomicAdd(&g_nstat[ch + 2], ls2); atomicAdd(&g_nstat[ch + 3], ls3);
    atomicAdd(&g_nstat[256 + ch + 0], lq0); atomicAdd(&g_nstat[256 + ch + 1], lq1);
    atomicAdd(&g_nstat[256 + ch + 2], lq2); atomicAdd(&g_nstat[256 + ch + 3], lq3);
}

// ---------------- batch-norm finalize + edge apply ---------------------------
__global__ void finalize_node_k(const float* __restrict__ gamma, const float* __restrict__ beta) {
    int c = threadIdx.x;
    float inv = 1.f / (float)NN;
    float m = g_nstat[c] * inv;
    float var = g_nstat[256 + c] * inv - m * m;
    float sc = gamma[c] * rsqrtf(var + EPSV);
    g_nscale[c] = sc;
    g_nscale[256 + c] = beta[c] - m * sc;
}

__global__ void finalize_edge_k(const float* __restrict__ gamma, const float* __restrict__ beta) {
    int c = threadIdx.x;
    float inv = 1.f / (float)EE;
    float m = g_estat[c] * inv;
    float var = g_estat[64 + c] * inv - m * m;
    float sc = gamma[c] * rsqrtf(var + EPSV);
    g_escale[c] = sc;
    g_escale[64 + c] = beta[c] - m * sc;
}

__global__ void apply_bn_edge_k(float* __restrict__ x) {
    size_t stride = (size_t)gridDim.x * blockDim.x;
    for (size_t i = (size_t)blockIdx.x * blockDim.x + threadIdx.x; i < (size_t)EE * 16; i += stride) {
        float4 v = ((float4*)x)[i];
        int c = (int)((i << 2) & 63);
        v.x = fmaf(v.x, g_escale[c + 0], g_escale[64 + c + 0]);
        v.y = fmaf(v.y, g_escale[c + 1], g_escale[64 + c + 1]);
        v.z = fmaf(v.z, g_escale[c + 2], g_escale[64 + c + 2]);
        v.w = fmaf(v.w, g_escale[c + 3], g_escale[64 + c + 3]);
        ((float4*)x)[i] = v;
    }
}

// ---------------- fused edge update on tensor cores (64-edge, pipelined) -----
#define WEE_H 0
#define WEE_L 9216
#define WF_H  18432
#define WF_L  36864
#define EI_H  55296
#define EI_L  64512
#define ACT_H 73728
#define ACT_L 91136
#define OFF_STAT 108544
#define EF5_SMEM 109056

__global__ __launch_bounds__(256, 2) void edge_final6_k(
    const float* __restrict__ EI, const int* __restrict__ src, const int* __restrict__ dst,
    const float* __restrict__ Wee, const float* __restrict__ Wf, float* __restrict__ out) {
    extern __shared__ char smem[];
    const uint32_t sb = smem_u32(smem);
    const int tid = threadIdx.x, lane = tid & 31, w = tid >> 5;
    float* sStat = (float*)(smem + OFF_STAT);

    for (int idx = tid; idx < 4096; idx += 256) {
        int r = idx >> 6, c = idx & 63;
        float v = Wee[idx];
        __nv_bfloat16 h = __float2bfloat16(v);
        *(__nv_bfloat16*)(smem + WEE_H + r * 144 + c * 2) = h;
        *(__nv_bfloat16*)(smem + WEE_L + r * 144 + c * 2) =
            __float2bfloat16(v - __bfloat162float(h));
    }
    for (int idx = tid; idx < 8192; idx += 256) {
        int r = idx >> 6, c = idx & 63;
        float v = Wf[idx];
        __nv_bfloat16 h = __float2bfloat16(v);
        *(__nv_bfloat16*)(smem + WF_H + r * 144 + c * 2) = h;
        *(__nv_bfloat16*)(smem + WF_L + r * 144 + c * 2) =
            __float2bfloat16(v - __bfloat162float(h));
    }
    if (tid < 128) sStat[tid] = 0.f;

    const int rl = lane & 15, ch16 = (lane >> 4) << 4;
    const int r0 = 16 * (w & 3);
    const int cg0 = (w >> 2) * 32;
    const int ra = r0 + (lane >> 2), rb = ra + 8;
    int pe[4], pc[4];
#pragma unroll
    for (int i = 0; i < 4; i++) { int idx = tid + i * 256; pe[i] = idx >> 4; pc[i] = idx & 15; }

    float sls[8], slq[8];
#pragma unroll
    for (int t = 0; t < 8; t++) { sls[t] = 0.f; slq[t] = 0.f; }

    // software pipeline: prefetch tile 0 into registers before the loop
    float4 eiv[4]; int sidx[4], didx[4];
    {
        int e0 = blockIdx.x * 64;
        if (e0 < EE) {
#pragma unroll
            for (int i = 0; i < 4; i++) {
                eiv[i]  = *(const float4*)(EI + (size_t)(e0 + pe[i]) * 64 + pc[i] * 4);
                sidx[i] = src[e0 + pe[i]];
                didx[i] = dst[e0 + pe[i]];
            }
        }
    }

    for (int e0 = blockIdx.x * 64; e0 < EE; e0 += gridDim.x * 64) {
        __syncthreads();   // prev-iter smem reads complete (and weight init on iter 0)

        // EI convert (prefetched regs) -> smem
#pragma unroll
        for (int i = 0; i < 4; i++) {
            float4 v = eiv[i];
            uint2 hu = make_uint2(f2bf2(v.x, v.y), f2bf2(v.z, v.w));
            float2 h01 = bf2f(hu.x), h23 = bf2f(hu.y);
            uint2 lu = make_uint2(f2bf2(v.x - h01.x, v.y - h01.y),
                                  f2bf2(v.z - h23.x, v.w - h23.y));
            *(uint2*)(smem + EI_H + pe[i] * 144 + pc[i] * 8) = hu;
            *(uint2*)(smem + EI_L + pe[i] * 144 + pc[i] * 8) = lu;
        }
        // node_f gather (prefetched indices) -> Act cols [0,64)
#pragma unroll
        for (int i = 0; i < 4; i++) {
            const float4 p = *(const float4*)(g_pq + (size_t)sidx[i] * 128 + pc[i] * 4);
            const float4 q = *(const float4*)(g_pq + (size_t)didx[i] * 128 + 64 + pc[i] * 4);
            float f0 = lrelu(p.x + q.x), f1 = lrelu(p.y + q.y);
            float f2 = lrelu(p.z + q.z), f3 = lrelu(p.w + q.w);
            uint2 hu = make_uint2(f2bf2(f0, f1), f2bf2(f2, f3));
            float2 h01 = bf2f(hu.x), h23 = bf2f(hu.y);
            uint2 lu = make_uint2(f2bf2(f0 - h01.x, f1 - h01.y),
                                  f2bf2(f2 - h23.x, f3 - h23.y));
            *(uint2*)(smem + ACT_H + pe[i] * 272 + pc[i] * 8) = hu;
            *(uint2*)(smem + ACT_L + pe[i] * 272 + pc[i] * 8) = lu;
        }

        // prefetch NEXT tile into the now-dead registers; latency hidden by stages
        {
            int en = e0 + gridDim.x * 64;
            if (en < EE) {
#pragma unroll
                for (int i = 0; i < 4; i++) {
                    eiv[i]  = *(const float4*)(EI + (size_t)(en + pe[i]) * 64 + pc[i] * 4);
                    sidx[i] = src[en + pe[i]];
                    didx[i] = dst[en + pe[i]];
                }
            }
        }
        __syncthreads();

        // stage1: edge_f = lrelu(EI @ Wee) -> Act cols [64,128), this warp's 32 cols
        {
            float c1[4][4];
#pragma unroll
            for (int nf = 0; nf < 4; nf++)
#pragma unroll
                for (int q = 0; q < 4; q++) c1[nf][q] = 0.f;
#pragma unroll
            for (int kk = 0; kk < 4; kk++) {
                uint32_t ah[4], al_[4];
                ldsm4(ah,  sb + EI_H + (r0 + rl) * 144 + ch16 + kk * 32);
                ldsm4(al_, sb + EI_L + (r0 + rl) * 144 + ch16 + kk * 32);
#pragma unroll
                for (int p = 0; p < 2; p++) {
                    uint32_t bh[4], bl_[4];
                    ldsm4t(bh,  sb + WEE_H + (kk * 16 + rl) * 144 + cg0 * 2 + p * 32 + ch16);
                    ldsm4t(bl_, sb + WEE_L + (kk * 16 + rl) * 144 + cg0 * 2 + p * 32 + ch16);
                    mma_bf16(c1[2 * p],     ah,  bh);
                    mma_bf16(c1[2 * p],     al_, bh);
                    mma_bf16(c1[2 * p],     ah,  bl_);
                    mma_bf16(c1[2 * p + 1], ah,  bh + 2);
                    mma_bf16(c1[2 * p + 1], al_, bh + 2);
                    mma_bf16(c1[2 * p + 1], ah,  bl_ + 2);
                }
            }
#pragma unroll
            for (int nf = 0; nf < 4; nf++) {
                int col = 64 + cg0 + nf * 8 + (lane & 3) * 2;
                float f0 = lrelu(c1[nf][0]), f1 = lrelu(c1[nf][1]);
                uint32_t h = f2bf2(f0, f1); float2 hh = bf2f(h);
                *(uint32_t*)(smem + ACT_H + ra * 272 + col * 2) = h;
                *(uint32_t*)(smem + ACT_L + ra * 272 + col * 2) = f2bf2(f0 - hh.x, f1 - hh.y);
                float f2 = lrelu(c1[nf][2]), f3 = lrelu(c1[nf][3]);
                uint32_t h2 = f2bf2(f2, f3); float2 hh2 = bf2f(h2);
                *(uint32_t*)(smem + ACT_H + rb * 272 + col * 2) = h2;
                *(uint32_t*)(smem + ACT_L + rb * 272 + col * 2) = f2bf2(f2 - hh2.x, f3 - hh2.y);
            }
        }
        __syncthreads();   // stage2 reads cols written by the other column-group warp

        // stage2: out = lrelu(Act @ Wf + EI), this warp's 32 cols
        {
            float c2[4][4];
#pragma unroll
            for (int nf = 0; nf < 4; nf++) {
                int col = cg0 + nf * 8 + (lane & 3) * 2;
                float2 ha = bf2f(*(uint32_t*)(smem + EI_H + ra * 144 + col * 2));
                float2 la = bf2f(*(uint32_t*)(smem + EI_L + ra * 144 + col * 2));
                float2 hb = bf2f(*(uint32_t*)(smem + EI_H + rb * 144 + col * 2));
                float2 lb = bf2f(*(uint32_t*)(smem + EI_L + rb * 144 + col * 2));
                c2[nf][0] = ha.x + la.x; c2[nf][1] = ha.y + la.y;
                c2[nf][2] = hb.x + lb.x; c2[nf][3] = hb.y + lb.y;
            }
#pragma unroll
            for (int kk = 0; kk < 8; kk++) {
                uint32_t ah[4], al_[4];
                ldsm4(ah,  sb + ACT_H + (r0 + rl) * 272 + ch16 + kk * 32);
                ldsm4(al_, sb + ACT_L + (r0 + rl) * 272 + ch16 + kk * 32);
#pragma unroll
                for (int p = 0; p < 2; p++) {
                    uint32_t bh[4], bl_[4];
                    ldsm4t(bh,  sb + WF_H + (kk * 16 + rl) * 144 + cg0 * 2 + p * 32 + ch16);
                    ldsm4t(bl_, sb + WF_L + (kk * 16 + rl) * 144 + cg0 * 2 + p * 32 + ch16);
                    mma_bf16(c2[2 * p],     ah,  bh);
                    mma_bf16(c2[2 * p],     al_, bh);
                    mma_bf16(c2[2 * p],     ah,  bl_);
                    mma_bf16(c2[2 * p + 1], ah,  bh + 2);
                    mma_bf16(c2[2 * p + 1], al_, bh + 2);
                    mma_bf16(c2[2 * p + 1], ah,  bl_ + 2);
                }
            }
#pragma unroll
            for (int nf = 0; nf < 4; nf++) {
                int col = cg0 + nf * 8 + (lane & 3) * 2;
                float o0 = lrelu(c2[nf][0]), o1 = lrelu(c2[nf][1]);
                float o2 = lrelu(c2[nf][2]), o3 = lrelu(c2[nf][3]);
                *(float2*)(out + (size_t)(e0 + ra) * 64 + col) = make_float2(o0, o1);
                *(float2*)(out + (size_t)(e0 + rb) * 64 + col) = make_float2(o2, o3);
                sls[nf * 2]     += o0 + o2; slq[nf * 2]     += o0 * o0 + o2 * o2;
                sls[nf * 2 + 1] += o1 + o3; slq[nf * 2 + 1] += o1 * o1 + o3 * o3;
            }
        }
    }

    __syncthreads();
#pragma unroll
    for (int t = 0; t < 8; t++) {
        int col = cg0 + (t >> 1) * 8 + (lane & 3) * 2 + (t & 1);
        atomicAdd(&sStat[col], sls[t]);
        atomicAdd(&sStat[64 + col], slq[t]);
    }
    __syncthreads();
    if (tid < 128) atomicAdd(&g_estat[tid], sStat[tid]);
}

// ---------------- side stream + events (created at load, outside checkpoints)
struct SideStream {
    cudaStream_t s = nullptr;
    cudaEvent_t fork = nullptr, mid = nullptr, join = nullptr;
    SideStream() {
        cudaStreamCreateWithFlags(&s, cudaStreamNonBlocking);
        cudaEventCreateWithFlags(&fork, cudaEventDisableTiming);
        cudaEventCreateWithFlags(&mid,  cudaEventDisableTiming);
        cudaEventCreateWithFlags(&join, cudaEventDisableTiming);
    }
};
static SideStream g_ss;

// ---------------- launch --------------------------------------------------------
extern "C" void kernel_launch(void* const* d_in, const int* in_sizes, int n_in,
                              void* d_out, int out_size) {
    const float* node_in    = (const float*)d_in[0];
    const float* edge_in    = (const float*)d_in[1];
    const float* fc_w       = (const float*)d_in[2];
    const float* attn_l     = (const float*)d_in[3];
    const float* attn_r     = (const float*)d_in[4];
    const float* ae_w1      = (const float*)d_in[5];
    const float* ae_b1      = (const float*)d_in[6];
    const float* ae_w2      = (const float*)d_in[7];
    const float* ae_b2      = (const float*)d_in[8];
    const float* bn_n_g     = (const float*)d_in[9];
    const float* bn_n_b     = (const float*)d_in[10];
    const float* eu_node_w  = (const float*)d_in[11];
    const float* eu_edge_w  = (const float*)d_in[12];
    const float* eu_final_w = (const float*)d_in[13];
    const float* bn_e_g     = (const float*)d_in[14];
    const float* bn_e_b     = (const float*)d_in[15];
    const int*   src        = (const int*)d_in[16];
    const int*   dst        = (const int*)d_in[17];

    float* out      = (float*)d_out;
    float* node_out = out;                       // [N, 256]
    float* edge_out = out + (size_t)NN * 256;    // [E, 64]

    float *p_ft, *p_pq, *p_pqw;
    cudaGetSymbolAddress((void**)&p_ft,  g_ft);
    cudaGetSymbolAddress((void**)&p_pq,  g_pq);
    cudaGetSymbolAddress((void**)&p_pqw, g_pqw);
    __nv_bfloat16 *p_ah, *p_al, *p_bh, *p_bl, *p_bh2, *p_bl2;
    cudaGetSymbolAddress((void**)&p_ah, g_ah);
    cudaGetSymbolAddress((void**)&p_al, g_al);
    cudaGetSymbolAddress((void**)&p_bh, g_bh);
    cudaGetSymbolAddress((void**)&p_bl, g_bl);
    cudaGetSymbolAddress((void**)&p_bh2, g_bh2);
    cudaGetSymbolAddress((void**)&p_bl2, g_bl2);

    const int GM_SMEM = 2 * 37888;
    cudaFuncSetAttribute(gemm_mma_k, cudaFuncAttributeMaxDynamicSharedMemorySize, GM_SMEM);
    cudaFuncSetAttribute(edge_final6_k, cudaFuncAttributeMaxDynamicSharedMemorySize, EF5_SMEM);

    cudaStream_t sB = g_ss.s;

    // fork: side stream handles CSR build + pqw prep + edge_attn
    cudaEventRecord(g_ss.fork, 0);
    cudaStreamWaitEvent(sB, g_ss.fork, 0);

    // ---- side stream: CSR chain + pqw split (own buffers: no race) ----
    zero_all_k<<<196, 256, 0, sB>>>();
    count_edges_k<<<(EE + 255) / 256, 256, 0, sB>>>(dst);
    scan_block_k<<<NB_SCAN, 1024, 0, sB>>>();
    finish_scan2_k<<<NB_SCAN, 1024, 0, sB>>>();
    scatter_k<<<(EE + 255) / 256, 256, 0, sB>>>(src, dst);
    build_pqw_k<<<128, 256, 0, sB>>>(eu_node_w);
    conv_b_k<<<128, 256, 0, sB>>>(p_pqw, p_bh2, p_bl2, 256 * 128);

    // ---- main stream: node features ----
    conv_b_k<<<256, 256>>>(fc_w, p_bh, p_bl, 256 * 256);
    build_fla_k<<<16, 256>>>(fc_w, attn_l, attn_r);
    conv_attn_k<<<6250, 256>>>(node_in);
    cudaEventRecord(g_ss.mid, 0);                      // a1/a2 + splits ready
    gemm_mma_k<<<dim3(2, 391), 256, GM_SMEM>>>(p_ah, p_al, p_bh, p_bl, p_ft, NN, 256);

    // ---- side stream: edge attention (needs a1/a2 + scatter) ----
    cudaStreamWaitEvent(sB, g_ss.mid, 0);
    edge_attn2_k<<<592, 256, 0, sB>>>(edge_in, ae_w1, ae_b1, ae_w2, ae_b2, src, dst);
    cudaEventRecord(g_ss.join, sB);

    // ---- join, then the dependent tail on main stream ----
    cudaStreamWaitEvent(0, g_ss.join, 0);
    node_agg_k<<<1184, 256>>>(node_in, node_out);
    finalize_node_k<<<1, 256>>>(bn_n_g, bn_n_b);
    conv_abn_k<<<25000, 256>>>(node_out);
    gemm_mma_k<<<dim3(1, 391), 256, GM_SMEM>>>(p_ah, p_al, p_bh2, p_bl2, p_pq, NN, 128);

    edge_final6_k<<<296, 256, EF5_SMEM>>>(edge_in, src, dst, eu_edge_w, eu_final_w, edge_out);
    finalize_edge_k<<<1, 64>>>(bn_e_g, bn_e_b);
    apply_bn_edge_k<<<4096, 256>>>(edge_out);
}

// round 16
// speedup vs baseline: 1.3833x; 1.3833x over previous
#include <cuda_runtime.h>
#include <cuda_bf16.h>
#include <cstdint>

#define NN 50000
#define EE 400000
#define ALPHA 0.2f
#define EPSV 1e-5f
#define NB_SCAN 49   // ceil(50000/1024)

// ---------------- scratch (device globals; no allocations allowed) ----------
__device__ float g_ft[(size_t)NN * 256];   // node projection [N,H,D]
__device__ float g_a1[NN * 8];
__device__ float g_a2[NN * 8];
__device__ float g_w [(size_t)EE * 8];     // exp(attn logits), CSR order [E,H]
__device__ float g_pq[(size_t)NN * 128];   // P|Q per node
__device__ float g_pqw[256 * 128];         // repacked eu_node_w
__device__ float g_fla[256 * 16];          // folded attn weights
__device__ int   g_counts[NN];
__device__ int   g_cursor[NN];
__device__ int   g_incl[NB_SCAN * 1024];
__device__ int   g_off[NN];
__device__ int   g_bsums[NB_SCAN];
__device__ int   g_srcc[EE];               // src[e] in CSR order
__device__ int   g_epos[EE];               // edge -> CSR position
__device__ float g_nstat[512];             // sum | sumsq (256 channels)
__device__ float g_nscale[512];            // scale | bias
__device__ float g_estat[128];             // sum | sumsq (64 channels)
__device__ float g_escale[128];
// bf16 split operands for tensor-core GEMMs
__device__ __nv_bfloat16 g_ah[(size_t)NN * 256];   // A hi, row-major [M,256]
__device__ __nv_bfloat16 g_al[(size_t)NN * 256];   // A lo
__device__ __nv_bfloat16 g_bh[256 * 256];          // B hi (fc_w)
__device__ __nv_bfloat16 g_bl[256 * 256];          // B lo (fc_w)
__device__ __nv_bfloat16 g_bh2[256 * 128];         // B hi (pqw) - separate buffers
__device__ __nv_bfloat16 g_bl2[256 * 128];         // B lo (pqw)

__device__ __forceinline__ float lrelu(float x) { return x > 0.f ? x : ALPHA * x; }

// ---------------- packed fp32x2 helpers --------------------------------------
typedef unsigned long long u64t;

#define FMA2(d, a, b) asm("fma.rn.f32x2 %0, %1, %2, %0;" : "+l"(d) : "l"(a), "l"(b))

__device__ __forceinline__ u64t fdup(float x) {
    u64t v; asm("mov.b64 %0, {%1, %1};" : "=l"(v) : "f"(x)); return v;
}
__device__ __forceinline__ u64t f2u(float x, float y) {
    u64t v; asm("mov.b64 %0, {%1, %2};" : "=l"(v) : "f"(x), "f"(y)); return v;
}
__device__ __forceinline__ float2 u2f(u64t v) {
    float2 f; asm("mov.b64 {%0, %1}, %2;" : "=f"(f.x), "=f"(f.y) : "l"(v)); return f;
}

// ---------------- mma.sync / ldmatrix / cp.async helpers ---------------------
__device__ __forceinline__ uint32_t smem_u32(const void* p) {
    uint32_t a;
    asm("{ .reg .u64 t; cvta.to.shared.u64 t, %1; cvt.u32.u64 %0, t; }" : "=r"(a) : "l"(p));
    return a;
}
__device__ __forceinline__ void ldsm4(uint32_t* r, uint32_t a) {
    asm volatile("ldmatrix.sync.aligned.m8n8.x4.shared.b16 {%0,%1,%2,%3}, [%4];"
        : "=r"(r[0]), "=r"(r[1]), "=r"(r[2]), "=r"(r[3]) : "r"(a));
}
__device__ __forceinline__ void ldsm4t(uint32_t* r, uint32_t a) {
    asm volatile("ldmatrix.sync.aligned.m8n8.x4.trans.shared.b16 {%0,%1,%2,%3}, [%4];"
        : "=r"(r[0]), "=r"(r[1]), "=r"(r[2]), "=r"(r[3]) : "r"(a));
}
__device__ __forceinline__ void mma_bf16(float* c, const uint32_t* a, const uint32_t* b) {
    asm volatile(
        "mma.sync.aligned.m16n8k16.row.col.f32.bf16.bf16.f32 "
        "{%0,%1,%2,%3}, {%4,%5,%6,%7}, {%8,%9}, {%0,%1,%2,%3};"
        : "+f"(c[0]), "+f"(c[1]), "+f"(c[2]), "+f"(c[3])
        : "r"(a[0]), "r"(a[1]), "r"(a[2]), "r"(a[3]), "r"(b[0]), "r"(b[1]));
}
#define CPASYNC(dst, src) \
    asm volatile("cp.async.ca.shared.global [%0], [%1], 16;" :: "r"(dst), "l"(src))
#define CPCOMMIT() asm volatile("cp.async.commit_group;" ::: "memory")

__device__ __forceinline__ uint32_t f2bf2(float x, float y) {
    __nv_bfloat162 b; b.x = __float2bfloat16(x); b.y = __float2bfloat16(y);
    uint32_t u; memcpy(&u, &b, 4); return u;
}
__device__ __forceinline__ float2 bf2f(uint32_t u) {
    __nv_bfloat162 b; memcpy(&b, &u, 4);
    return make_float2(__bfloat162float(b.x), __bfloat162float(b.y));
}

// ---------------- zero per-launch state -------------------------------------
__global__ void zero_all_k() {
    int i = blockIdx.x * blockDim.x + threadIdx.x;
    if (i < NN) { g_counts[i] = 0; g_cursor[i] = 0; }
    if (i < 512) g_nstat[i] = 0.f;
    if (i < 128) g_estat[i] = 0.f;
}

// ---------------- repack eu_node_w [512,64] -> [256,128] (P|Q) --------------
__global__ void build_pqw_k(const float* __restrict__ W) {
    int i = blockIdx.x * blockDim.x + threadIdx.x;
    if (i >= 256 * 128) return;
    int k = i >> 7, j = i & 127;
    g_pqw[i] = (j < 64) ? W[(k << 6) + j] : W[((256 + k) << 6) + (j - 64)];
}

// ---------------- fold attn vectors through fc_w: fla[k][o] ------------------
__global__ void build_fla_k(const float* __restrict__ fc_w, const float* __restrict__ al,
                            const float* __restrict__ ar) {
    int idx = blockIdx.x * blockDim.x + threadIdx.x;
    if (idx >= 4096) return;
    int k = idx >> 4, o = idx & 15;
    const float* w = fc_w + k * 256;
    const float* v = (o < 8) ? (al + (o << 5)) : (ar + ((o - 8) << 5));
    const float* wb = w + ((o & 7) << 5);
    float s = 0.f;
#pragma unroll
    for (int d = 0; d < 32; d++) s = fmaf(wb[d], v[d], s);
    g_fla[k * 16 + o] = s;
}

// ---------------- fused: node_in bf16 hi/lo split + a1,a2 dots ---------------
__global__ void conv_attn_k(const float* __restrict__ X) {
    __shared__ float sFla[256 * 17];
    for (int i = threadIdx.x; i < 4096; i += 256) {
        int k = i >> 4, o = i & 15;
        sFla[k * 17 + o] = g_fla[i];
    }
    __syncthreads();
    int n = blockIdx.x * 8 + (threadIdx.x >> 5);
    if (n >= NN) return;
    int lane = threadIdx.x & 31;
    const float* xr = X + (size_t)n * 256 + lane * 8;
    float4 v0 = *(const float4*)xr;
    float4 v1 = *(const float4*)(xr + 4);
    float xv[8] = {v0.x, v0.y, v0.z, v0.w, v1.x, v1.y, v1.z, v1.w};

    __nv_bfloat162* ahp = (__nv_bfloat162*)g_ah + (size_t)n * 128 + lane * 4;
    __nv_bfloat162* alp = (__nv_bfloat162*)g_al + (size_t)n * 128 + lane * 4;
#pragma unroll
    for (int j = 0; j < 4; j++) {
        float a = xv[2 * j], b = xv[2 * j + 1];
        __nv_bfloat162 hp; hp.x = __float2bfloat16(a); hp.y = __float2bfloat16(b);
        __nv_bfloat162 lp;
        lp.x = __float2bfloat16(a - __bfloat162float(hp.x));
        lp.y = __float2bfloat16(b - __bfloat162float(hp.y));
        ahp[j] = hp; alp[j] = lp;
    }

    float acc[16];
#pragma unroll
    for (int o = 0; o < 16; o++) acc[o] = 0.f;
#pragma unroll
    for (int j = 0; j < 8; j++) {
        const float* f = &sFla[(lane * 8 + j) * 17];
        float x = xv[j];
#pragma unroll
        for (int o = 0; o < 16; o++) acc[o] = fmaf(x, f[o], acc[o]);
    }
#pragma unroll
    for (int off = 16; off; off >>= 1)
#pragma unroll
        for (int o = 0; o < 16; o++) acc[o] += __shfl_xor_sync(0xffffffffu, acc[o], off);
    if (lane < 8)       g_a1[n * 8 + lane] = acc[lane];
    else if (lane < 16) g_a2[n * 8 + (lane - 8)] = acc[lane];
}

// fused: BN-node apply (in place) + bf16 hi/lo split
__global__ void conv_abn_k(float* __restrict__ X) {
    int i = blockIdx.x * blockDim.x + threadIdx.x;
    if (i >= NN * 128) return;
    float2 v = ((float2*)X)[i];
    int c = (i << 1) & 255;
    v.x = fmaf(v.x, g_nscale[c],     g_nscale[256 + c]);
    v.y = fmaf(v.y, g_nscale[c + 1], g_nscale[256 + c + 1]);
    ((float2*)X)[i] = v;
    __nv_bfloat16 h0 = __float2bfloat16(v.x);
    __nv_bfloat16 h1 = __float2bfloat16(v.y);
    __nv_bfloat162 hp; hp.x = h0; hp.y = h1;
    __nv_bfloat162 lp;
    lp.x = __float2bfloat16(v.x - __bfloat162float(h0));
    lp.y = __float2bfloat16(v.y - __bfloat162float(h1));
    ((__nv_bfloat162*)g_ah)[i] = hp;
    ((__nv_bfloat162*)g_al)[i] = lp;
}

// W [K,N] fp32 -> bh/bl (parameterized destination)
__global__ void conv_b_k(const float* __restrict__ W, __nv_bfloat16* __restrict__ BH,
                         __nv_bfloat16* __restrict__ BL, int total) {
    int i = blockIdx.x * blockDim.x + threadIdx.x;
    if (i >= total) return;
    float v = W[i];
    __nv_bfloat16 h = __float2bfloat16(v);
    BH[i] = h;
    BL[i] = __float2bfloat16(v - __bfloat162float(h));
}

// ---------------- tensor-core GEMM via mma.sync (bf16 3-term split) ----------
__global__ __launch_bounds__(256, 2) void gemm_mma_k(
    const __nv_bfloat16* __restrict__ Ah, const __nv_bfloat16* __restrict__ Al,
    const __nv_bfloat16* __restrict__ Bh, const __nv_bfloat16* __restrict__ Bl,
    float* __restrict__ C, int M, int Nsz) {
    extern __shared__ char smem[];
    const int tid = threadIdx.x, lane = tid & 31, w = tid >> 5;
    const int wm = w >> 1, wn = w & 1;
    const int row0 = blockIdx.y * 128, col0 = blockIdx.x * 128;
    const uint32_t sb = smem_u32(smem);
    const int BUF = 37888;

    float acc[2][8][4];
#pragma unroll
    for (int i = 0; i < 2; i++)
#pragma unroll
        for (int j = 0; j < 8; j++)
#pragma unroll
            for (int q = 0; q < 4; q++) acc[i][j][q] = 0.f;

    uint32_t a_base[2][2], b_base[2][4];
    {
        int rl = lane & 15, ch = (lane >> 4) << 4;
#pragma unroll
        for (int t = 0; t < 2; t++)
#pragma unroll
            for (int mf = 0; mf < 2; mf++)
                a_base[t][mf] = t * 10240 + (wm * 32 + mf * 16 + rl) * 80 + ch;
#pragma unroll
        for (int t = 0; t < 2; t++)
#pragma unroll
            for (int p = 0; p < 4; p++)
                b_base[t][p] = 20480 + t * 8704 + rl * 272 + wn * 128 + p * 32 + ch;
    }

    auto stage = [&](int kc, int bb) {
        uint32_t dbase = sb + bb * BUF;
#pragma unroll
        for (int i = 0; i < 4; i++) {
            int idx = tid + i * 256;
            int t = idx >> 9, c = idx & 511;
            int r = c >> 2, kch = c & 3;
            int gr = row0 + r; if (gr >= M) gr = M - 1;
            const char* src = (const char*)(t ? Al : Ah)
                            + ((size_t)gr * 256 + kc * 32 + kch * 8) * 2;
            CPASYNC(dbase + t * 10240 + r * 80 + kch * 16, src);
        }
#pragma unroll
        for (int i = 0; i < 4; i++) {
            int idx = tid + i * 256;
            int t = idx >> 9, c = idx & 511;
            int kr = c >> 4, nch = c & 15;
            const char* src = (const char*)(t ? Bl : Bh)
                            + ((size_t)(kc * 32 + kr) * Nsz + col0 + nch * 8) * 2;
            CPASYNC(dbase + 20480 + t * 8704 + kr * 272 + nch * 16, src);
        }
        CPCOMMIT();
    };

    const int NK = 8;
    stage(0, 0);
    stage(1, 1);

    for (int kc = 0; kc < NK; kc++) {
        int bb = kc & 1;
        if (kc == NK - 1) asm volatile("cp.async.wait_group 0;" ::: "memory");
        else              asm volatile("cp.async.wait_group 1;" ::: "memory");
        __syncthreads();
        uint32_t base = sb + bb * BUF;
#pragma unroll
        for (int ks = 0; ks < 2; ks++) {
            uint32_t ah[2][4], al_[2][4];
            ldsm4(ah[0],  base + a_base[0][0] + ks * 32);
            ldsm4(ah[1],  base + a_base[0][1] + ks * 32);
            ldsm4(al_[0], base + a_base[1][0] + ks * 32);
            ldsm4(al_[1], base + a_base[1][1] + ks * 32);
#pragma unroll
            for (int p = 0; p < 4; p++) {
                uint32_t bh[4], bl_[4];
                ldsm4t(bh,  base + b_base[0][p] + ks * 4352);
                ldsm4t(bl_, base + b_base[1][p] + ks * 4352);
#pragma unroll
                for (int mf = 0; mf < 2; mf++) {
                    mma_bf16(acc[mf][2 * p],     ah[mf],  bh);
                    mma_bf16(acc[mf][2 * p],     al_[mf], bh);
                    mma_bf16(acc[mf][2 * p],     ah[mf],  bl_);
                    mma_bf16(acc[mf][2 * p + 1], ah[mf],  bh + 2);
                    mma_bf16(acc[mf][2 * p + 1], al_[mf], bh + 2);
                    mma_bf16(acc[mf][2 * p + 1], ah[mf],  bl_ + 2);
                }
            }
        }
        __syncthreads();
        if (kc + 2 < NK) stage(kc + 2, bb);
    }

    const int cc = col0 + wn * 64 + (lane & 3) * 2;
#pragma unroll
    for (int mf = 0; mf < 2; mf++) {
        int ra = row0 + wm * 32 + mf * 16 + (lane >> 2);
        int rb = ra + 8;
#pragma unroll
        for (int nf = 0; nf < 8; nf++) {
            int col = cc + nf * 8;
            if (ra < M) *(float2*)(C + (size_t)ra * Nsz + col)
                          = make_float2(acc[mf][nf][0], acc[mf][nf][1]);
            if (rb < M) *(float2*)(C + (size_t)rb * Nsz + col)
                          = make_float2(acc[mf][nf][2], acc[mf][nf][3]);
        }
    }
}

// ---------------- CSR build ---------------------------------------------------
__global__ void count_edges_k(const int* __restrict__ dst) {
    int e = blockIdx.x * blockDim.x + threadIdx.x;
    if (e < EE) atomicAdd(&g_counts[dst[e]], 1);
}

__global__ void scan_block_k() {
    __shared__ int sh[1024];
    int i = blockIdx.x * 1024 + threadIdx.x;
    int v = (i < NN) ? g_counts[i] : 0;
    sh[threadIdx.x] = v;
    __syncthreads();
    for (int off = 1; off < 1024; off <<= 1) {
        int t = (threadIdx.x >= off) ? sh[threadIdx.x - off] : 0;
        __syncthreads();
        sh[threadIdx.x] += t;
        __syncthreads();
    }
    g_incl[i] = sh[threadIdx.x];
    if (threadIdx.x == 1023) g_bsums[blockIdx.x] = sh[1023];
}

__global__ void finish_scan2_k() {
    __shared__ int sh[64];
    int tid = threadIdx.x;
    if (tid < 64)
        sh[tid] = (tid < NB_SCAN && tid < (int)blockIdx.x) ? g_bsums[tid] : 0;
    __syncthreads();
    if (tid < 32) {
        int v = sh[tid] + sh[tid + 32];
#pragma unroll
        for (int off = 16; off; off >>= 1) v += __shfl_down_sync(0xffffffffu, v, off);
        if (tid == 0) sh[0] = v;
    }
    __syncthreads();
    int base = sh[0];
    int i = blockIdx.x * 1024 + tid;
    if (i < NN) g_off[i] = g_incl[i] - g_counts[i] + base;
}

__global__ void scatter_k(const int* __restrict__ src, const int* __restrict__ dst) {
    int e = blockIdx.x * blockDim.x + threadIdx.x;
    if (e < EE) {
        int d = dst[e];
        int p = atomicAdd(&g_cursor[d], 1);
        int pos = g_off[d] + p;
        g_srcc[pos] = src[e];
        g_epos[e] = pos;
    }
}

// ---------------- edge attention MLP as block-tiled FMA2 GEMM ----------------
#define EIP2 68
__global__ void edge_attn2_k(const float* __restrict__ EI, const float* __restrict__ w1,
                             const float* __restrict__ b1, const float* __restrict__ w2,
                             const float* __restrict__ b2, const int* __restrict__ src,
                             const int* __restrict__ dst) {
    __shared__ float sW1[64 * 32];
    __shared__ float sW2[32 * 8];
    __shared__ float sB1[32];
    __shared__ float sB2[8];
    __shared__ float sEI[128 * EIP2];
    __shared__ float sH[128 * 36];
    for (int i = threadIdx.x; i < 2048; i += 256) sW1[i] = w1[i];
    if (threadIdx.x < 256) sW2[threadIdx.x] = w2[threadIdx.x];
    if (threadIdx.x < 32)  sB1[threadIdx.x] = b1[threadIdx.x];
    if (threadIdx.x < 8)   sB2[threadIdx.x] = b2[threadIdx.x];

    const int cg = threadIdx.x & 7;
    const int er = threadIdx.x >> 3;
    const int c0 = cg << 2;
    const int eb = er << 2;

    for (int e0 = blockIdx.x * 128; e0 < EE; e0 += gridDim.x * 128) {
        __syncthreads();
        for (int idx = threadIdx.x; idx < 128 * 16; idx += 256) {
            int e = idx >> 4, c4 = (idx & 15) << 2;
            *(float4*)&sEI[e * EIP2 + c4] = *(const float4*)(EI + (size_t)(e0 + e) * 64 + c4);
        }
        __syncthreads();

        u64t acc[4][2];
        u64t bA = f2u(sB1[c0], sB1[c0 + 1]);
        u64t bB = f2u(sB1[c0 + 2], sB1[c0 + 3]);
#pragma unroll
        for (int i = 0; i < 4; i++) { acc[i][0] = bA; acc[i][1] = bB; }
#pragma unroll 8
        for (int k = 0; k < 64; k++) {
            u64t w01 = *(const u64t*)&sW1[(k << 5) + c0];
            u64t w23 = *(const u64t*)&sW1[(k << 5) + c0 + 2];
#pragma unroll
            for (int i = 0; i < 4; i++) {
                u64t av = fdup(sEI[(eb + i) * EIP2 + k]);
                FMA2(acc[i][0], av, w01);
                FMA2(acc[i][1], av, w23);
            }
        }
#pragma unroll
        for (int i = 0; i < 4; i++) {
            float2 f0 = u2f(acc[i][0]), f1 = u2f(acc[i][1]);
            float* hp = &sH[(eb + i) * 36 + c0];
            hp[0] = lrelu(f0.x); hp[1] = lrelu(f0.y);
            hp[2] = lrelu(f1.x); hp[3] = lrelu(f1.y);
        }
        __syncthreads();

#pragma unroll
        for (int i = 0; i < 4; i++) {
            int e = e0 + eb + i;
            float o = sB2[cg];
#pragma unroll 8
            for (int k = 0; k < 32; k++)
                o = fmaf(sH[(eb + i) * 36 + k], sW2[(k << 3) + cg], o);
            int sN = src[e], dN = dst[e];
            float v = lrelu(o + g_a1[sN * 8 + cg] + g_a2[dN * 8 + cg]);
            g_w[(size_t)g_epos[e] * 8 + cg] = expf(v);
        }
    }
}

// ---------------- per-node aggregation (CSR streaming, 8-way MLP) ------------
__global__ void node_agg_k(const float* __restrict__ xin, float* __restrict__ xout) {
    const int t = threadIdx.x & 63;
    const int head = t >> 3;
    const int g = threadIdx.x >> 6;
    const int ch = t << 2;
    float ls0 = 0, ls1 = 0, ls2 = 0, ls3 = 0, lq0 = 0, lq1 = 0, lq2 = 0, lq3 = 0;
    for (int n = blockIdx.x * 4 + g; n < NN; n += gridDim.x * 4) {
        float a0 = 0, a1 = 0, a2 = 0, a3 = 0, zl = 0;
        int j = g_off[n];
        int j1 = j + g_counts[n];
        while (j + 8 <= j1) {
            int s[8]; float wv[8]; float4 v[8];
#pragma unroll
            for (int u = 0; u < 8; u++) {
                s[u]  = g_srcc[j + u];
                wv[u] = g_w[(size_t)(j + u) * 8 + head];
            }
#pragma unroll
            for (int u = 0; u < 8; u++)
                v[u] = *(const float4*)(g_ft + (size_t)s[u] * 256 + ch);
#pragma unroll
            for (int u = 0; u < 8; u++) {
                a0 = fmaf(v[u].x, wv[u], a0); a1 = fmaf(v[u].y, wv[u], a1);
                a2 = fmaf(v[u].z, wv[u], a2); a3 = fmaf(v[u].w, wv[u], a3);
            }
            if ((t & 7) == 0)
                zl += wv[0] + wv[1] + wv[2] + wv[3] + wv[4] + wv[5] + wv[6] + wv[7];
            j += 8;
        }
        while (j < j1) {
            int s = g_srcc[j];
            float wv = g_w[(size_t)j * 8 + head];
            const float4 v = *(const float4*)(g_ft + (size_t)s * 256 + ch);
            a0 = fmaf(v.x, wv, a0); a1 = fmaf(v.y, wv, a1);
            a2 = fmaf(v.z, wv, a2); a3 = fmaf(v.w, wv, a3);
            if ((t & 7) == 0) zl += wv;
            j++;
        }
        float z = __shfl_sync(0xffffffffu, zl, (threadIdx.x & 31) & 24);
        if (z == 0.f) z = 1.f;
        float inv = 1.f / z;
        const float4 xi = *(const float4*)(xin + (size_t)n * 256 + ch);
        float x0 = lrelu(fmaf(a0, inv, xi.x));
        float x1 = lrelu(fmaf(a1, inv, xi.y));
        float x2 = lrelu(fmaf(a2, inv, xi.z));
        float x3 = lrelu(fmaf(a3, inv, xi.w));
        *(float4*)(xout + (size_t)n * 256 + ch) = make_float4(x0, x1, x2, x3);
        ls0 += x0; ls1 += x1; ls2 += x2; ls3 += x3;
        lq0 += x0 * x0; lq1 += x1 * x1; lq2 += x2 * x2; lq3 += x3 * x3;
    }
    atomicAdd(&g_nstat[ch + 0], ls0); atomicAdd(&g_nstat[ch + 1], ls1);
    atomicAdd(&g_nstat[ch + 2], ls2); atomicAdd(&g_nstat[ch + 3], ls3);
    atomicAdd(&g_nstat[256 + ch + 0], lq0); atomicAdd(&g_nstat[256 + ch + 1], lq1);
    atomicAdd(&g_nstat[256 + ch + 2], lq2); atomicAdd(&g_nstat[256 + ch + 3], lq3);
}

// ---------------- batch-norm finalize + edge apply ---------------------------
__global__ void finalize_node_k(const float* __restrict__ gamma, const float* __restrict__ beta) {
    int c = threadIdx.x;
    float inv = 1.f / (float)NN;
    float m = g_nstat[c] * inv;
    float var = g_nstat[256 + c] * inv - m * m;
    float sc = gamma[c] * rsqrtf(var + EPSV);
    g_nscale[c] = sc;
    g_nscale[256 + c] = beta[c] - m * sc;
}

__global__ void finalize_edge_k(const float* __restrict__ gamma, const float* __restrict__ beta) {
    int c = threadIdx.x;
    float inv = 1.f / (float)EE;
    float m = g_estat[c] * inv;
    float var = g_estat[64 + c] * inv - m * m;
    float sc = gamma[c] * rsqrtf(var + EPSV);
    g_escale[c] = sc;
    g_escale[64 + c] = beta[c] - m * sc;
}

__global__ void apply_bn_edge_k(float* __restrict__ x) {
    size_t stride = (size_t)gridDim.x * blockDim.x;
    for (size_t i = (size_t)blockIdx.x * blockDim.x + threadIdx.x; i < (size_t)EE * 16; i += stride) {
        float4 v = ((float4*)x)[i];
        int c = (int)((i << 2) & 63);
        v.x = fmaf(v.x, g_escale[c + 0], g_escale[64 + c + 0]);
        v.y = fmaf(v.y, g_escale[c + 1], g_escale[64 + c + 1]);
        v.z = fmaf(v.z, g_escale[c + 2], g_escale[64 + c + 2]);
        v.w = fmaf(v.w, g_escale[c + 3], g_escale[64 + c + 3]);
        ((float4*)x)[i] = v;
    }
}

// ---------------- fused edge update on tensor cores (64-edge, pipelined) -----
#define WEE_H 0
#define WEE_L 9216
#define WF_H  18432
#define WF_L  36864
#define EI_H  55296
#define EI_L  64512
#define ACT_H 73728
#define ACT_L 91136
#define OFF_STAT 108544
#define EF5_SMEM 109056

__global__ __launch_bounds__(256, 2) void edge_final6_k(
    const float* __restrict__ EI, const int* __restrict__ src, const int* __restrict__ dst,
    const float* __restrict__ Wee, const float* __restrict__ Wf, float* __restrict__ out) {
    extern __shared__ char smem[];
    const uint32_t sb = smem_u32(smem);
    const int tid = threadIdx.x, lane = tid & 31, w = tid >> 5;
    float* sStat = (float*)(smem + OFF_STAT);

    for (int idx = tid; idx < 4096; idx += 256) {
        int r = idx >> 6, c = idx & 63;
        float v = Wee[idx];
        __nv_bfloat16 h = __float2bfloat16(v);
        *(__nv_bfloat16*)(smem + WEE_H + r * 144 + c * 2) = h;
        *(__nv_bfloat16*)(smem + WEE_L + r * 144 + c * 2) =
            __float2bfloat16(v - __bfloat162float(h));
    }
    for (int idx = tid; idx < 8192; idx += 256) {
        int r = idx >> 6, c = idx & 63;
        float v = Wf[idx];
        __nv_bfloat16 h = __float2bfloat16(v);
        *(__nv_bfloat16*)(smem + WF_H + r * 144 + c * 2) = h;
        *(__nv_bfloat16*)(smem + WF_L + r * 144 + c * 2) =
            __float2bfloat16(v - __bfloat162float(h));
    }
    if (tid < 128) sStat[tid] = 0.f;

    const int rl = lane & 15, ch16 = (lane >> 4) << 4;
    const int r0 = 16 * (w & 3);
    const int cg0 = (w >> 2) * 32;
    const int ra = r0 + (lane >> 2), rb = ra + 8;
    int pe[4], pc[4];
#pragma unroll
    for (int i = 0; i < 4; i++) { int idx = tid + i * 256; pe[i] = idx >> 4; pc[i] = idx & 15; }

    float sls[8], slq[8];
#pragma unroll
    for (int t = 0; t < 8; t++) { sls[t] = 0.f; slq[t] = 0.f; }

    // software pipeline: prefetch tile 0 into registers before the loop
    float4 eiv[4]; int sidx[4], didx[4];
    {
        int e0 = blockIdx.x * 64;
        if (e0 < EE) {
#pragma unroll
            for (int i = 0; i < 4; i++) {
                eiv[i]  = *(const float4*)(EI + (size_t)(e0 + pe[i]) * 64 + pc[i] * 4);
                sidx[i] = src[e0 + pe[i]];
                didx[i] = dst[e0 + pe[i]];
            }
        }
    }

    for (int e0 = blockIdx.x * 64; e0 < EE; e0 += gridDim.x * 64) {
        __syncthreads();   // prev-iter smem reads complete (and weight init on iter 0)

        // EI convert (prefetched regs) -> smem
#pragma unroll
        for (int i = 0; i < 4; i++) {
            float4 v = eiv[i];
            uint2 hu = make_uint2(f2bf2(v.x, v.y), f2bf2(v.z, v.w));
            float2 h01 = bf2f(hu.x), h23 = bf2f(hu.y);
            uint2 lu = make_uint2(f2bf2(v.x - h01.x, v.y - h01.y),
                                  f2bf2(v.z - h23.x, v.w - h23.y));
            *(uint2*)(smem + EI_H + pe[i] * 144 + pc[i] * 8) = hu;
            *(uint2*)(smem + EI_L + pe[i] * 144 + pc[i] * 8) = lu;
        }
        // node_f gather (prefetched indices) -> Act cols [0,64)
#pragma unroll
        for (int i = 0; i < 4; i++) {
            const float4 p = *(const float4*)(g_pq + (size_t)sidx[i] * 128 + pc[i] * 4);
            const float4 q = *(const float4*)(g_pq + (size_t)didx[i] * 128 + 64 + pc[i] * 4);
            float f0 = lrelu(p.x + q.x), f1 = lrelu(p.y + q.y);
            float f2 = lrelu(p.z + q.z), f3 = lrelu(p.w + q.w);
            uint2 hu = make_uint2(f2bf2(f0, f1), f2bf2(f2, f3));
            float2 h01 = bf2f(hu.x), h23 = bf2f(hu.y);
            uint2 lu = make_uint2(f2bf2(f0 - h01.x, f1 - h01.y),
                                  f2bf2(f2 - h23.x, f3 - h23.y));
            *(uint2*)(smem + ACT_H + pe[i] * 272 + pc[i] * 8) = hu;
            *(uint2*)(smem + ACT_L + pe[i] * 272 + pc[i] * 8) = lu;
        }

        // prefetch NEXT tile into the now-dead registers; latency hidden by stages
        {
            int en = e0 + gridDim.x * 64;
            if (en < EE) {
#pragma unroll
                for (int i = 0; i < 4; i++) {
                    eiv[i]  = *(const float4*)(EI + (size_t)(en + pe[i]) * 64 + pc[i] * 4);
                    sidx[i] = src[en + pe[i]];
                    didx[i] = dst[en + pe[i]];
                }
            }
        }
        __syncthreads();

        // stage1: edge_f = lrelu(EI @ Wee) -> Act cols [64,128), this warp's 32 cols
        {
            float c1[4][4];
#pragma unroll
            for (int nf = 0; nf < 4; nf++)
#pragma unroll
                for (int q = 0; q < 4; q++) c1[nf][q] = 0.f;
#pragma unroll
            for (int kk = 0; kk < 4; kk++) {
                uint32_t ah[4], al_[4];
                ldsm4(ah,  sb + EI_H + (r0 + rl) * 144 + ch16 + kk * 32);
                ldsm4(al_, sb + EI_L + (r0 + rl) * 144 + ch16 + kk * 32);
#pragma unroll
                for (int p = 0; p < 2; p++) {
                    uint32_t bh[4], bl_[4];
                    ldsm4t(bh,  sb + WEE_H + (kk * 16 + rl) * 144 + cg0 * 2 + p * 32 + ch16);
                    ldsm4t(bl_, sb + WEE_L + (kk * 16 + rl) * 144 + cg0 * 2 + p * 32 + ch16);
                    mma_bf16(c1[2 * p],     ah,  bh);
                    mma_bf16(c1[2 * p],     al_, bh);
                    mma_bf16(c1[2 * p],     ah,  bl_);
                    mma_bf16(c1[2 * p + 1], ah,  bh + 2);
                    mma_bf16(c1[2 * p + 1], al_, bh + 2);
                    mma_bf16(c1[2 * p + 1], ah,  bl_ + 2);
                }
            }
#pragma unroll
            for (int nf = 0; nf < 4; nf++) {
                int col = 64 + cg0 + nf * 8 + (lane & 3) * 2;
                float f0 = lrelu(c1[nf][0]), f1 = lrelu(c1[nf][1]);
                uint32_t h = f2bf2(f0, f1); float2 hh = bf2f(h);
                *(uint32_t*)(smem + ACT_H + ra * 272 + col * 2) = h;
                *(uint32_t*)(smem + ACT_L + ra * 272 + col * 2) = f2bf2(f0 - hh.x, f1 - hh.y);
                float f2 = lrelu(c1[nf][2]), f3 = lrelu(c1[nf][3]);
                uint32_t h2 = f2bf2(f2, f3); float2 hh2 = bf2f(h2);
                *(uint32_t*)(smem + ACT_H + rb * 272 + col * 2) = h2;
                *(uint32_t*)(smem + ACT_L + rb * 272 + col * 2) = f2bf2(f2 - hh2.x, f3 - hh2.y);
            }
        }
        __syncthreads();   // stage2 reads cols written by the other column-group warp

        // stage2: out = lrelu(Act @ Wf + EI), this warp's 32 cols
        {
            float c2[4][4];
#pragma unroll
            for (int nf = 0; nf < 4; nf++) {
                int col = cg0 + nf * 8 + (lane & 3) * 2;
                float2 ha = bf2f(*(uint32_t*)(smem + EI_H + ra * 144 + col * 2));
                float2 la = bf2f(*(uint32_t*)(smem + EI_L + ra * 144 + col * 2));
                float2 hb = bf2f(*(uint32_t*)(smem + EI_H + rb * 144 + col * 2));
                float2 lb = bf2f(*(uint32_t*)(smem + EI_L + rb * 144 + col * 2));
                c2[nf][0] = ha.x + la.x; c2[nf][1] = ha.y + la.y;
                c2[nf][2] = hb.x + lb.x; c2[nf][3] = hb.y + lb.y;
            }
#pragma unroll
            for (int kk = 0; kk < 8; kk++) {
                uint32_t ah[4], al_[4];
                ldsm4(ah,  sb + ACT_H + (r0 + rl) * 272 + ch16 + kk * 32);
                ldsm4(al_, sb + ACT_L + (r0 + rl) * 272 + ch16 + kk * 32);
#pragma unroll
                for (int p = 0; p < 2; p++) {
                    uint32_t bh[4], bl_[4];
                    ldsm4t(bh,  sb + WF_H + (kk * 16 + rl) * 144 + cg0 * 2 + p * 32 + ch16);
                    ldsm4t(bl_, sb + WF_L + (kk * 16 + rl) * 144 + cg0 * 2 + p * 32 + ch16);
                    mma_bf16(c2[2 * p],     ah,  bh);
                    mma_bf16(c2[2 * p],     al_, bh);
                    mma_bf16(c2[2 * p],     ah,  bl_);
                    mma_bf16(c2[2 * p + 1], ah,  bh + 2);
                    mma_bf16(c2[2 * p + 1], al_, bh + 2);
                    mma_bf16(c2[2 * p + 1], ah,  bl_ + 2);
                }
            }
#pragma unroll
            for (int nf = 0; nf < 4; nf++) {
                int col = cg0 + nf * 8 + (lane & 3) * 2;
                float o0 = lrelu(c2[nf][0]), o1 = lrelu(c2[nf][1]);
                float o2 = lrelu(c2[nf][2]), o3 = lrelu(c2[nf][3]);
                *(float2*)(out + (size_t)(e0 + ra) * 64 + col) = make_float2(o0, o1);
                *(float2*)(out + (size_t)(e0 + rb) * 64 + col) = make_float2(o2, o3);
                sls[nf * 2]     += o0 + o2; slq[nf * 2]     += o0 * o0 + o2 * o2;
                sls[nf * 2 + 1] += o1 + o3; slq[nf * 2 + 1] += o1 * o1 + o3 * o3;
            }
        }
    }

    __syncthreads();
#pragma unroll
    for (int t = 0; t < 8; t++) {
        int col = cg0 + (t >> 1) * 8 + (lane & 3) * 2 + (t & 1);
        atomicAdd(&sStat[col], sls[t]);
        atomicAdd(&sStat[64 + col], slq[t]);
    }
    __syncthreads();
    if (tid < 128) atomicAdd(&g_estat[tid], sStat[tid]);
}

// ---------------- side stream + events (created at load, outside checkpoints)
struct SideStream {
    cudaStream_t s = nullptr;
    cudaEvent_t fork = nullptr, mid = nullptr, join = nullptr;
    SideStream() {
        cudaStreamCreateWithFlags(&s, cudaStreamNonBlocking);
        cudaEventCreateWithFlags(&fork, cudaEventDisableTiming);
        cudaEventCreateWithFlags(&mid,  cudaEventDisableTiming);
        cudaEventCreateWithFlags(&join, cudaEventDisableTiming);
    }
};
static SideStream g_ss;

// ---------------- launch --------------------------------------------------------
extern "C" void kernel_launch(void* const* d_in, const int* in_sizes, int n_in,
                              void* d_out, int out_size) {
    const float* node_in    = (const float*)d_in[0];
    const float* edge_in    = (const float*)d_in[1];
    const float* fc_w       = (const float*)d_in[2];
    const float* attn_l     = (const float*)d_in[3];
    const float* attn_r     = (const float*)d_in[4];
    const float* ae_w1      = (const float*)d_in[5];
    const float* ae_b1      = (const float*)d_in[6];
    const float* ae_w2      = (const float*)d_in[7];
    const float* ae_b2      = (const float*)d_in[8];
    const float* bn_n_g     = (const float*)d_in[9];
    const float* bn_n_b     = (const float*)d_in[10];
    const float* eu_node_w  = (const float*)d_in[11];
    const float* eu_edge_w  = (const float*)d_in[12];
    const float* eu_final_w = (const float*)d_in[13];
    const float* bn_e_g     = (const float*)d_in[14];
    const float* bn_e_b     = (const float*)d_in[15];
    const int*   src        = (const int*)d_in[16];
    const int*   dst        = (const int*)d_in[17];

    float* out      = (float*)d_out;
    float* node_out = out;                       // [N, 256]
    float* edge_out = out + (size_t)NN * 256;    // [E, 64]

    float *p_ft, *p_pq, *p_pqw;
    cudaGetSymbolAddress((void**)&p_ft,  g_ft);
    cudaGetSymbolAddress((void**)&p_pq,  g_pq);
    cudaGetSymbolAddress((void**)&p_pqw, g_pqw);
    __nv_bfloat16 *p_ah, *p_al, *p_bh, *p_bl, *p_bh2, *p_bl2;
    cudaGetSymbolAddress((void**)&p_ah, g_ah);
    cudaGetSymbolAddress((void**)&p_al, g_al);
    cudaGetSymbolAddress((void**)&p_bh, g_bh);
    cudaGetSymbolAddress((void**)&p_bl, g_bl);
    cudaGetSymbolAddress((void**)&p_bh2, g_bh2);
    cudaGetSymbolAddress((void**)&p_bl2, g_bl2);

    const int GM_SMEM = 2 * 37888;
    cudaFuncSetAttribute(gemm_mma_k, cudaFuncAttributeMaxDynamicSharedMemorySize, GM_SMEM);
    cudaFuncSetAttribute(edge_final6_k, cudaFuncAttributeMaxDynamicSharedMemorySize, EF5_SMEM);

    cudaStream_t sB = g_ss.s;

    // fork: side stream handles CSR build + pqw prep + edge_attn
    cudaEventRecord(g_ss.fork, 0);
    cudaStreamWaitEvent(sB, g_ss.fork, 0);

    // ---- side stream: CSR chain + pqw split (own buffers: no race) ----
    zero_all_k<<<196, 256, 0, sB>>>();
    count_edges_k<<<(EE + 255) / 256, 256, 0, sB>>>(dst);
    scan_block_k<<<NB_SCAN, 1024, 0, sB>>>();
    finish_scan2_k<<<NB_SCAN, 1024, 0, sB>>>();
    scatter_k<<<(EE + 255) / 256, 256, 0, sB>>>(src, dst);
    build_pqw_k<<<128, 256, 0, sB>>>(eu_node_w);
    conv_b_k<<<128, 256, 0, sB>>>(p_pqw, p_bh2, p_bl2, 256 * 128);

    // ---- main stream: node features ----
    conv_b_k<<<256, 256>>>(fc_w, p_bh, p_bl, 256 * 256);
    build_fla_k<<<16, 256>>>(fc_w, attn_l, attn_r);
    conv_attn_k<<<6250, 256>>>(node_in);
    cudaEventRecord(g_ss.mid, 0);                      // a1/a2 + splits ready
    gemm_mma_k<<<dim3(2, 391), 256, GM_SMEM>>>(p_ah, p_al, p_bh, p_bl, p_ft, NN, 256);

    // ---- side stream: edge attention (needs a1/a2 + scatter) ----
    cudaStreamWaitEvent(sB, g_ss.mid, 0);
    edge_attn2_k<<<592, 256, 0, sB>>>(edge_in, ae_w1, ae_b1, ae_w2, ae_b2, src, dst);
    cudaEventRecord(g_ss.join, sB);

    // ---- join, then the dependent tail on main stream ----
    cudaStreamWaitEvent(0, g_ss.join, 0);
    node_agg_k<<<1184, 256>>>(node_in, node_out);
    finalize_node_k<<<1, 256>>>(bn_n_g, bn_n_b);
    conv_abn_k<<<25000, 256>>>(node_out);
    gemm_mma_k<<<dim3(1, 391), 256, GM_SMEM>>>(p_ah, p_al, p_bh2, p_bl2, p_pq, NN, 128);

    edge_final6_k<<<296, 256, EF5_SMEM>>>(edge_in, src, dst, eu_edge_w, eu_final_w, edge_out);
    finalize_edge_k<<<1, 64>>>(bn_e_g, bn_e_b);
    apply_bn_edge_k<<<4096, 256>>>(edge_out);
}

// round 17
// speedup vs baseline: 1.3874x; 1.0030x over previous
#include <cuda_runtime.h>
#include <cuda_bf16.h>
#include <cstdint>

#define NN 50000
#define EE 400000
#define ALPHA 0.2f
#define EPSV 1e-5f
#define NB_SCAN 49   // ceil(50000/1024)

// ---------------- scratch (device globals; no allocations allowed) ----------
__device__ float g_ft[(size_t)NN * 256];   // node projection [N,H,D]
__device__ float g_a1[NN * 8];
__device__ float g_a2[NN * 8];
__device__ float g_w [(size_t)EE * 8];     // exp(attn logits), CSR order [E,H]
__device__ float g_pq[(size_t)NN * 128];   // P|Q per node
__device__ float g_pqw[256 * 128];         // repacked eu_node_w
__device__ float g_fla[256 * 16];          // folded attn weights
__device__ int   g_counts[NN];
__device__ int   g_cursor[NN];
__device__ int   g_incl[NB_SCAN * 1024];
__device__ int   g_off[NN];
__device__ int   g_bsums[NB_SCAN];
__device__ int   g_srcc[EE];               // src[e] in CSR order
__device__ int   g_epos[EE];               // edge -> CSR position
__device__ float g_nstat[512];             // sum | sumsq (256 channels)
__device__ float g_nscale[512];            // scale | bias
__device__ float g_estat[128];             // sum | sumsq (64 channels)
__device__ float g_escale[128];
// bf16 split operands for tensor-core GEMMs
__device__ __nv_bfloat16 g_ah[(size_t)NN * 256];   // A hi, row-major [M,256]
__device__ __nv_bfloat16 g_al[(size_t)NN * 256];   // A lo
__device__ __nv_bfloat16 g_bh[256 * 256];          // B hi (fc_w)
__device__ __nv_bfloat16 g_bl[256 * 256];          // B lo (fc_w)
__device__ __nv_bfloat16 g_bh2[256 * 128];         // B hi (pqw) - separate buffers
__device__ __nv_bfloat16 g_bl2[256 * 128];         // B lo (pqw)

__device__ __forceinline__ float lrelu(float x) { return x > 0.f ? x : ALPHA * x; }

// ---------------- packed fp32x2 helpers --------------------------------------
typedef unsigned long long u64t;

#define FMA2(d, a, b) asm("fma.rn.f32x2 %0, %1, %2, %0;" : "+l"(d) : "l"(a), "l"(b))

__device__ __forceinline__ u64t fdup(float x) {
    u64t v; asm("mov.b64 %0, {%1, %1};" : "=l"(v) : "f"(x)); return v;
}
__device__ __forceinline__ u64t f2u(float x, float y) {
    u64t v; asm("mov.b64 %0, {%1, %2};" : "=l"(v) : "f"(x), "f"(y)); return v;
}
__device__ __forceinline__ float2 u2f(u64t v) {
    float2 f; asm("mov.b64 {%0, %1}, %2;" : "=f"(f.x), "=f"(f.y) : "l"(v)); return f;
}

// ---------------- mma.sync / ldmatrix / cp.async helpers ---------------------
__device__ __forceinline__ uint32_t smem_u32(const void* p) {
    uint32_t a;
    asm("{ .reg .u64 t; cvta.to.shared.u64 t, %1; cvt.u32.u64 %0, t; }" : "=r"(a) : "l"(p));
    return a;
}
__device__ __forceinline__ void ldsm4(uint32_t* r, uint32_t a) {
    asm volatile("ldmatrix.sync.aligned.m8n8.x4.shared.b16 {%0,%1,%2,%3}, [%4];"
        : "=r"(r[0]), "=r"(r[1]), "=r"(r[2]), "=r"(r[3]) : "r"(a));
}
__device__ __forceinline__ void ldsm4t(uint32_t* r, uint32_t a) {
    asm volatile("ldmatrix.sync.aligned.m8n8.x4.trans.shared.b16 {%0,%1,%2,%3}, [%4];"
        : "=r"(r[0]), "=r"(r[1]), "=r"(r[2]), "=r"(r[3]) : "r"(a));
}
__device__ __forceinline__ void mma_bf16(float* c, const uint32_t* a, const uint32_t* b) {
    asm volatile(
        "mma.sync.aligned.m16n8k16.row.col.f32.bf16.bf16.f32 "
        "{%0,%1,%2,%3}, {%4,%5,%6,%7}, {%8,%9}, {%0,%1,%2,%3};"
        : "+f"(c[0]), "+f"(c[1]), "+f"(c[2]), "+f"(c[3])
        : "r"(a[0]), "r"(a[1]), "r"(a[2]), "r"(a[3]), "r"(b[0]), "r"(b[1]));
}
#define CPASYNC(dst, src) \
    asm volatile("cp.async.ca.shared.global [%0], [%1], 16;" :: "r"(dst), "l"(src))
#define CPCOMMIT() asm volatile("cp.async.commit_group;" ::: "memory")

__device__ __forceinline__ uint32_t f2bf2(float x, float y) {
    __nv_bfloat162 b; b.x = __float2bfloat16(x); b.y = __float2bfloat16(y);
    uint32_t u; memcpy(&u, &b, 4); return u;
}
__device__ __forceinline__ float2 bf2f(uint32_t u) {
    __nv_bfloat162 b; memcpy(&b, &u, 4);
    return make_float2(__bfloat162float(b.x), __bfloat162float(b.y));
}

// ---------------- zero per-launch state -------------------------------------
__global__ void zero_all_k() {
    int i = blockIdx.x * blockDim.x + threadIdx.x;
    if (i < NN) { g_counts[i] = 0; g_cursor[i] = 0; }
    if (i < 512) g_nstat[i] = 0.f;
    if (i < 128) g_estat[i] = 0.f;
}

// ---------------- repack eu_node_w [512,64] -> [256,128] (P|Q) --------------
__global__ void build_pqw_k(const float* __restrict__ W) {
    int i = blockIdx.x * blockDim.x + threadIdx.x;
    if (i >= 256 * 128) return;
    int k = i >> 7, j = i & 127;
    g_pqw[i] = (j < 64) ? W[(k << 6) + j] : W[((256 + k) << 6) + (j - 64)];
}

// ---------------- fold attn vectors through fc_w: fla[k][o] ------------------
__global__ void build_fla_k(const float* __restrict__ fc_w, const float* __restrict__ al,
                            const float* __restrict__ ar) {
    int idx = blockIdx.x * blockDim.x + threadIdx.x;
    if (idx >= 4096) return;
    int k = idx >> 4, o = idx & 15;
    const float* w = fc_w + k * 256;
    const float* v = (o < 8) ? (al + (o << 5)) : (ar + ((o - 8) << 5));
    const float* wb = w + ((o & 7) << 5);
    float s = 0.f;
#pragma unroll
    for (int d = 0; d < 32; d++) s = fmaf(wb[d], v[d], s);
    g_fla[k * 16 + o] = s;
}

// ---------------- fused: node_in bf16 hi/lo split + a1,a2 dots ---------------
__global__ void conv_attn_k(const float* __restrict__ X) {
    __shared__ float sFla[256 * 17];
    for (int i = threadIdx.x; i < 4096; i += 256) {
        int k = i >> 4, o = i & 15;
        sFla[k * 17 + o] = g_fla[i];
    }
    __syncthreads();
    int n = blockIdx.x * 8 + (threadIdx.x >> 5);
    if (n >= NN) return;
    int lane = threadIdx.x & 31;
    const float* xr = X + (size_t)n * 256 + lane * 8;
    float4 v0 = *(const float4*)xr;
    float4 v1 = *(const float4*)(xr + 4);
    float xv[8] = {v0.x, v0.y, v0.z, v0.w, v1.x, v1.y, v1.z, v1.w};

    __nv_bfloat162* ahp = (__nv_bfloat162*)g_ah + (size_t)n * 128 + lane * 4;
    __nv_bfloat162* alp = (__nv_bfloat162*)g_al + (size_t)n * 128 + lane * 4;
#pragma unroll
    for (int j = 0; j < 4; j++) {
        float a = xv[2 * j], b = xv[2 * j + 1];
        __nv_bfloat162 hp; hp.x = __float2bfloat16(a); hp.y = __float2bfloat16(b);
        __nv_bfloat162 lp;
        lp.x = __float2bfloat16(a - __bfloat162float(hp.x));
        lp.y = __float2bfloat16(b - __bfloat162float(hp.y));
        ahp[j] = hp; alp[j] = lp;
    }

    float acc[16];
#pragma unroll
    for (int o = 0; o < 16; o++) acc[o] = 0.f;
#pragma unroll
    for (int j = 0; j < 8; j++) {
        const float* f = &sFla[(lane * 8 + j) * 17];
        float x = xv[j];
#pragma unroll
        for (int o = 0; o < 16; o++) acc[o] = fmaf(x, f[o], acc[o]);
    }
#pragma unroll
    for (int off = 16; off; off >>= 1)
#pragma unroll
        for (int o = 0; o < 16; o++) acc[o] += __shfl_xor_sync(0xffffffffu, acc[o], off);
    if (lane < 8)       g_a1[n * 8 + lane] = acc[lane];
    else if (lane < 16) g_a2[n * 8 + (lane - 8)] = acc[lane];
}

// fused: BN-node apply (in place) + bf16 hi/lo split
__global__ void conv_abn_k(float* __restrict__ X) {
    int i = blockIdx.x * blockDim.x + threadIdx.x;
    if (i >= NN * 128) return;
    float2 v = ((float2*)X)[i];
    int c = (i << 1) & 255;
    v.x = fmaf(v.x, g_nscale[c],     g_nscale[256 + c]);
    v.y = fmaf(v.y, g_nscale[c + 1], g_nscale[256 + c + 1]);
    ((float2*)X)[i] = v;
    __nv_bfloat16 h0 = __float2bfloat16(v.x);
    __nv_bfloat16 h1 = __float2bfloat16(v.y);
    __nv_bfloat162 hp; hp.x = h0; hp.y = h1;
    __nv_bfloat162 lp;
    lp.x = __float2bfloat16(v.x - __bfloat162float(h0));
    lp.y = __float2bfloat16(v.y - __bfloat162float(h1));
    ((__nv_bfloat162*)g_ah)[i] = hp;
    ((__nv_bfloat162*)g_al)[i] = lp;
}

// W [K,N] fp32 -> bh/bl (parameterized destination)
__global__ void conv_b_k(const float* __restrict__ W, __nv_bfloat16* __restrict__ BH,
                         __nv_bfloat16* __restrict__ BL, int total) {
    int i = blockIdx.x * blockDim.x + threadIdx.x;
    if (i >= total) return;
    float v = W[i];
    __nv_bfloat16 h = __float2bfloat16(v);
    BH[i] = h;
    BL[i] = __float2bfloat16(v - __bfloat162float(h));
}

// ---------------- tensor-core GEMM via mma.sync (bf16 3-term split) ----------
__global__ __launch_bounds__(256, 2) void gemm_mma_k(
    const __nv_bfloat16* __restrict__ Ah, const __nv_bfloat16* __restrict__ Al,
    const __nv_bfloat16* __restrict__ Bh, const __nv_bfloat16* __restrict__ Bl,
    float* __restrict__ C, int M, int Nsz) {
    extern __shared__ char smem[];
    const int tid = threadIdx.x, lane = tid & 31, w = tid >> 5;
    const int wm = w >> 1, wn = w & 1;
    const int row0 = blockIdx.y * 128, col0 = blockIdx.x * 128;
    const uint32_t sb = smem_u32(smem);
    const int BUF = 37888;

    float acc[2][8][4];
#pragma unroll
    for (int i = 0; i < 2; i++)
#pragma unroll
        for (int j = 0; j < 8; j++)
#pragma unroll
            for (int q = 0; q < 4; q++) acc[i][j][q] = 0.f;

    uint32_t a_base[2][2], b_base[2][4];
    {
        int rl = lane & 15, ch = (lane >> 4) << 4;
#pragma unroll
        for (int t = 0; t < 2; t++)
#pragma unroll
            for (int mf = 0; mf < 2; mf++)
                a_base[t][mf] = t * 10240 + (wm * 32 + mf * 16 + rl) * 80 + ch;
#pragma unroll
        for (int t = 0; t < 2; t++)
#pragma unroll
            for (int p = 0; p < 4; p++)
                b_base[t][p] = 20480 + t * 8704 + rl * 272 + wn * 128 + p * 32 + ch;
    }

    auto stage = [&](int kc, int bb) {
        uint32_t dbase = sb + bb * BUF;
#pragma unroll
        for (int i = 0; i < 4; i++) {
            int idx = tid + i * 256;
            int t = idx >> 9, c = idx & 511;
            int r = c >> 2, kch = c & 3;
            int gr = row0 + r; if (gr >= M) gr = M - 1;
            const char* src = (const char*)(t ? Al : Ah)
                            + ((size_t)gr * 256 + kc * 32 + kch * 8) * 2;
            CPASYNC(dbase + t * 10240 + r * 80 + kch * 16, src);
        }
#pragma unroll
        for (int i = 0; i < 4; i++) {
            int idx = tid + i * 256;
            int t = idx >> 9, c = idx & 511;
            int kr = c >> 4, nch = c & 15;
            const char* src = (const char*)(t ? Bl : Bh)
                            + ((size_t)(kc * 32 + kr) * Nsz + col0 + nch * 8) * 2;
            CPASYNC(dbase + 20480 + t * 8704 + kr * 272 + nch * 16, src);
        }
        CPCOMMIT();
    };

    const int NK = 8;
    stage(0, 0);
    stage(1, 1);

    for (int kc = 0; kc < NK; kc++) {
        int bb = kc & 1;
        if (kc == NK - 1) asm volatile("cp.async.wait_group 0;" ::: "memory");
        else              asm volatile("cp.async.wait_group 1;" ::: "memory");
        __syncthreads();
        uint32_t base = sb + bb * BUF;
#pragma unroll
        for (int ks = 0; ks < 2; ks++) {
            uint32_t ah[2][4], al_[2][4];
            ldsm4(ah[0],  base + a_base[0][0] + ks * 32);
            ldsm4(ah[1],  base + a_base[0][1] + ks * 32);
            ldsm4(al_[0], base + a_base[1][0] + ks * 32);
            ldsm4(al_[1], base + a_base[1][1] + ks * 32);
#pragma unroll
            for (int p = 0; p < 4; p++) {
                uint32_t bh[4], bl_[4];
                ldsm4t(bh,  base + b_base[0][p] + ks * 4352);
                ldsm4t(bl_, base + b_base[1][p] + ks * 4352);
#pragma unroll
                for (int mf = 0; mf < 2; mf++) {
                    mma_bf16(acc[mf][2 * p],     ah[mf],  bh);
                    mma_bf16(acc[mf][2 * p],     al_[mf], bh);
                    mma_bf16(acc[mf][2 * p],     ah[mf],  bl_);
                    mma_bf16(acc[mf][2 * p + 1], ah[mf],  bh + 2);
                    mma_bf16(acc[mf][2 * p + 1], al_[mf], bh + 2);
                    mma_bf16(acc[mf][2 * p + 1], ah[mf],  bl_ + 2);
                }
            }
        }
        __syncthreads();
        if (kc + 2 < NK) stage(kc + 2, bb);
    }

    const int cc = col0 + wn * 64 + (lane & 3) * 2;
#pragma unroll
    for (int mf = 0; mf < 2; mf++) {
        int ra = row0 + wm * 32 + mf * 16 + (lane >> 2);
        int rb = ra + 8;
#pragma unroll
        for (int nf = 0; nf < 8; nf++) {
            int col = cc + nf * 8;
            if (ra < M) *(float2*)(C + (size_t)ra * Nsz + col)
                          = make_float2(acc[mf][nf][0], acc[mf][nf][1]);
            if (rb < M) *(float2*)(C + (size_t)rb * Nsz + col)
                          = make_float2(acc[mf][nf][2], acc[mf][nf][3]);
        }
    }
}

// ---------------- CSR build ---------------------------------------------------
__global__ void count_edges_k(const int* __restrict__ dst) {
    int e = blockIdx.x * blockDim.x + threadIdx.x;
    if (e < EE) atomicAdd(&g_counts[dst[e]], 1);
}

__global__ void scan_block_k() {
    __shared__ int sh[1024];
    int i = blockIdx.x * 1024 + threadIdx.x;
    int v = (i < NN) ? g_counts[i] : 0;
    sh[threadIdx.x] = v;
    __syncthreads();
    for (int off = 1; off < 1024; off <<= 1) {
        int t = (threadIdx.x >= off) ? sh[threadIdx.x - off] : 0;
        __syncthreads();
        sh[threadIdx.x] += t;
        __syncthreads();
    }
    g_incl[i] = sh[threadIdx.x];
    if (threadIdx.x == 1023) g_bsums[blockIdx.x] = sh[1023];
}

__global__ void finish_scan2_k() {
    __shared__ int sh[64];
    int tid = threadIdx.x;
    if (tid < 64)
        sh[tid] = (tid < NB_SCAN && tid < (int)blockIdx.x) ? g_bsums[tid] : 0;
    __syncthreads();
    if (tid < 32) {
        int v = sh[tid] + sh[tid + 32];
#pragma unroll
        for (int off = 16; off; off >>= 1) v += __shfl_down_sync(0xffffffffu, v, off);
        if (tid == 0) sh[0] = v;
    }
    __syncthreads();
    int base = sh[0];
    int i = blockIdx.x * 1024 + tid;
    if (i < NN) g_off[i] = g_incl[i] - g_counts[i] + base;
}

__global__ void scatter_k(const int* __restrict__ src, const int* __restrict__ dst) {
    int e = blockIdx.x * blockDim.x + threadIdx.x;
    if (e < EE) {
        int d = dst[e];
        int p = atomicAdd(&g_cursor[d], 1);
        int pos = g_off[d] + p;
        g_srcc[pos] = src[e];
        g_epos[e] = pos;
    }
}

// ---------------- edge attention MLP as block-tiled FMA2 GEMM ----------------
#define EIP2 68
__global__ void edge_attn2_k(const float* __restrict__ EI, const float* __restrict__ w1,
                             const float* __restrict__ b1, const float* __restrict__ w2,
                             const float* __restrict__ b2, const int* __restrict__ src,
                             const int* __restrict__ dst) {
    __shared__ float sW1[64 * 32];
    __shared__ float sW2[32 * 8];
    __shared__ float sB1[32];
    __shared__ float sB2[8];
    __shared__ float sEI[128 * EIP2];
    __shared__ float sH[128 * 36];
    for (int i = threadIdx.x; i < 2048; i += 256) sW1[i] = w1[i];
    if (threadIdx.x < 256) sW2[threadIdx.x] = w2[threadIdx.x];
    if (threadIdx.x < 32)  sB1[threadIdx.x] = b1[threadIdx.x];
    if (threadIdx.x < 8)   sB2[threadIdx.x] = b2[threadIdx.x];

    const int cg = threadIdx.x & 7;
    const int er = threadIdx.x >> 3;
    const int c0 = cg << 2;
    const int eb = er << 2;

    for (int e0 = blockIdx.x * 128; e0 < EE; e0 += gridDim.x * 128) {
        __syncthreads();
        for (int idx = threadIdx.x; idx < 128 * 16; idx += 256) {
            int e = idx >> 4, c4 = (idx & 15) << 2;
            *(float4*)&sEI[e * EIP2 + c4] = *(const float4*)(EI + (size_t)(e0 + e) * 64 + c4);
        }
        __syncthreads();

        u64t acc[4][2];
        u64t bA = f2u(sB1[c0], sB1[c0 + 1]);
        u64t bB = f2u(sB1[c0 + 2], sB1[c0 + 3]);
#pragma unroll
        for (int i = 0; i < 4; i++) { acc[i][0] = bA; acc[i][1] = bB; }
#pragma unroll 8
        for (int k = 0; k < 64; k++) {
            u64t w01 = *(const u64t*)&sW1[(k << 5) + c0];
            u64t w23 = *(const u64t*)&sW1[(k << 5) + c0 + 2];
#pragma unroll
            for (int i = 0; i < 4; i++) {
                u64t av = fdup(sEI[(eb + i) * EIP2 + k]);
                FMA2(acc[i][0], av, w01);
                FMA2(acc[i][1], av, w23);
            }
        }
#pragma unroll
        for (int i = 0; i < 4; i++) {
            float2 f0 = u2f(acc[i][0]), f1 = u2f(acc[i][1]);
            float* hp = &sH[(eb + i) * 36 + c0];
            hp[0] = lrelu(f0.x); hp[1] = lrelu(f0.y);
            hp[2] = lrelu(f1.x); hp[3] = lrelu(f1.y);
        }
        __syncthreads();

#pragma unroll
        for (int i = 0; i < 4; i++) {
            int e = e0 + eb + i;
            float o = sB2[cg];
#pragma unroll 8
            for (int k = 0; k < 32; k++)
                o = fmaf(sH[(eb + i) * 36 + k], sW2[(k << 3) + cg], o);
            int sN = src[e], dN = dst[e];
            float v = lrelu(o + g_a1[sN * 8 + cg] + g_a2[dN * 8 + cg]);
            g_w[(size_t)g_epos[e] * 8 + cg] = expf(v);
        }
    }
}

// ---------------- per-node aggregation (CSR streaming, 8-way MLP) ------------
__global__ void node_agg_k(const float* __restrict__ xin, float* __restrict__ xout) {
    const int t = threadIdx.x & 63;
    const int head = t >> 3;
    const int g = threadIdx.x >> 6;
    const int ch = t << 2;
    float ls0 = 0, ls1 = 0, ls2 = 0, ls3 = 0, lq0 = 0, lq1 = 0, lq2 = 0, lq3 = 0;
    for (int n = blockIdx.x * 4 + g; n < NN; n += gridDim.x * 4) {
        float a0 = 0, a1 = 0, a2 = 0, a3 = 0, zl = 0;
        int j = g_off[n];
        int j1 = j + g_counts[n];
        while (j + 8 <= j1) {
            int s[8]; float wv[8]; float4 v[8];
#pragma unroll
            for (int u = 0; u < 8; u++) {
                s[u]  = g_srcc[j + u];
                wv[u] = g_w[(size_t)(j + u) * 8 + head];
            }
#pragma unroll
            for (int u = 0; u < 8; u++)
                v[u] = *(const float4*)(g_ft + (size_t)s[u] * 256 + ch);
#pragma unroll
            for (int u = 0; u < 8; u++) {
                a0 = fmaf(v[u].x, wv[u], a0); a1 = fmaf(v[u].y, wv[u], a1);
                a2 = fmaf(v[u].z, wv[u], a2); a3 = fmaf(v[u].w, wv[u], a3);
            }
            if ((t & 7) == 0)
                zl += wv[0] + wv[1] + wv[2] + wv[3] + wv[4] + wv[5] + wv[6] + wv[7];
            j += 8;
        }
        while (j < j1) {
            int s = g_srcc[j];
            float wv = g_w[(size_t)j * 8 + head];
            const float4 v = *(const float4*)(g_ft + (size_t)s * 256 + ch);
            a0 = fmaf(v.x, wv, a0); a1 = fmaf(v.y, wv, a1);
            a2 = fmaf(v.z, wv, a2); a3 = fmaf(v.w, wv, a3);
            if ((t & 7) == 0) zl += wv;
            j++;
        }
        float z = __shfl_sync(0xffffffffu, zl, (threadIdx.x & 31) & 24);
        if (z == 0.f) z = 1.f;
        float inv = 1.f / z;
        const float4 xi = *(const float4*)(xin + (size_t)n * 256 + ch);
        float x0 = lrelu(fmaf(a0, inv, xi.x));
        float x1 = lrelu(fmaf(a1, inv, xi.y));
        float x2 = lrelu(fmaf(a2, inv, xi.z));
        float x3 = lrelu(fmaf(a3, inv, xi.w));
        *(float4*)(xout + (size_t)n * 256 + ch) = make_float4(x0, x1, x2, x3);
        ls0 += x0; ls1 += x1; ls2 += x2; ls3 += x3;
        lq0 += x0 * x0; lq1 += x1 * x1; lq2 += x2 * x2; lq3 += x3 * x3;
    }
    atomicAdd(&g_nstat[ch + 0], ls0); atomicAdd(&g_nstat[ch + 1], ls1);
    atomicAdd(&g_nstat[ch + 2], ls2); atomicAdd(&g_nstat[ch + 3], ls3);
    atomicAdd(&g_nstat[256 + ch + 0], lq0); atomicAdd(&g_nstat[256 + ch + 1], lq1);
    atomicAdd(&g_nstat[256 + ch + 2], lq2); atomicAdd(&g_nstat[256 + ch + 3], lq3);
}

// ---------------- batch-norm finalize + edge apply ---------------------------
__global__ void finalize_node_k(const float* __restrict__ gamma, const float* __restrict__ beta) {
    int c = threadIdx.x;
    float inv = 1.f / (float)NN;
    float m = g_nstat[c] * inv;
    float var = g_nstat[256 + c] * inv - m * m;
    float sc = gamma[c] * rsqrtf(var + EPSV);
    g_nscale[c] = sc;
    g_nscale[256 + c] = beta[c] - m * sc;
}

__global__ void finalize_edge_k(const float* __restrict__ gamma, const float* __restrict__ beta) {
    int c = threadIdx.x;
    float inv = 1.f / (float)EE;
    float m = g_estat[c] * inv;
    float var = g_estat[64 + c] * inv - m * m;
    float sc = gamma[c] * rsqrtf(var + EPSV);
    g_escale[c] = sc;
    g_escale[64 + c] = beta[c] - m * sc;
}

__global__ void apply_bn_edge_k(float* __restrict__ x) {
    size_t stride = (size_t)gridDim.x * blockDim.x;
    for (size_t i = (size_t)blockIdx.x * blockDim.x + threadIdx.x; i < (size_t)EE * 16; i += stride) {
        float4 v = ((float4*)x)[i];
        int c = (int)((i << 2) & 63);
        v.x = fmaf(v.x, g_escale[c + 0], g_escale[64 + c + 0]);
        v.y = fmaf(v.y, g_escale[c + 1], g_escale[64 + c + 1]);
        v.z = fmaf(v.z, g_escale[c + 2], g_escale[64 + c + 2]);
        v.w = fmaf(v.w, g_escale[c + 3], g_escale[64 + c + 3]);
        ((float4*)x)[i] = v;
    }
}

// ---------------- fused edge update on tensor cores (64-edge, pipelined) -----
#define WEE_H 0
#define WEE_L 9216
#define WF_H  18432
#define WF_L  36864
#define EI_H  55296
#define EI_L  64512
#define ACT_H 73728
#define ACT_L 91136
#define OFF_STAT 108544
#define EF5_SMEM 109056

__global__ __launch_bounds__(256, 2) void edge_final6_k(
    const float* __restrict__ EI, const int* __restrict__ src, const int* __restrict__ dst,
    const float* __restrict__ Wee, const float* __restrict__ Wf, float* __restrict__ out) {
    extern __shared__ char smem[];
    const uint32_t sb = smem_u32(smem);
    const int tid = threadIdx.x, lane = tid & 31, w = tid >> 5;
    float* sStat = (float*)(smem + OFF_STAT);

    for (int idx = tid; idx < 4096; idx += 256) {
        int r = idx >> 6, c = idx & 63;
        float v = Wee[idx];
        __nv_bfloat16 h = __float2bfloat16(v);
        *(__nv_bfloat16*)(smem + WEE_H + r * 144 + c * 2) = h;
        *(__nv_bfloat16*)(smem + WEE_L + r * 144 + c * 2) =
            __float2bfloat16(v - __bfloat162float(h));
    }
    for (int idx = tid; idx < 8192; idx += 256) {
        int r = idx >> 6, c = idx & 63;
        float v = Wf[idx];
        __nv_bfloat16 h = __float2bfloat16(v);
        *(__nv_bfloat16*)(smem + WF_H + r * 144 + c * 2) = h;
        *(__nv_bfloat16*)(smem + WF_L + r * 144 + c * 2) =
            __float2bfloat16(v - __bfloat162float(h));
    }
    if (tid < 128) sStat[tid] = 0.f;

    const int rl = lane & 15, ch16 = (lane >> 4) << 4;
    const int r0 = 16 * (w & 3);
    const int cg0 = (w >> 2) * 32;
    const int ra = r0 + (lane >> 2), rb = ra + 8;
    int pe[4], pc[4];
#pragma unroll
    for (int i = 0; i < 4; i++) { int idx = tid + i * 256; pe[i] = idx >> 4; pc[i] = idx & 15; }

    float sls[8], slq[8];
#pragma unroll
    for (int t = 0; t < 8; t++) { sls[t] = 0.f; slq[t] = 0.f; }

    // software pipeline: prefetch tile 0 into registers before the loop
    float4 eiv[4]; int sidx[4], didx[4];
    {
        int e0 = blockIdx.x * 64;
        if (e0 < EE) {
#pragma unroll
            for (int i = 0; i < 4; i++) {
                eiv[i]  = *(const float4*)(EI + (size_t)(e0 + pe[i]) * 64 + pc[i] * 4);
                sidx[i] = src[e0 + pe[i]];
                didx[i] = dst[e0 + pe[i]];
            }
        }
    }

    for (int e0 = blockIdx.x * 64; e0 < EE; e0 += gridDim.x * 64) {
        __syncthreads();   // prev-iter smem reads complete (and weight init on iter 0)

        // EI convert (prefetched regs) -> smem
#pragma unroll
        for (int i = 0; i < 4; i++) {
            float4 v = eiv[i];
            uint2 hu = make_uint2(f2bf2(v.x, v.y), f2bf2(v.z, v.w));
            float2 h01 = bf2f(hu.x), h23 = bf2f(hu.y);
            uint2 lu = make_uint2(f2bf2(v.x - h01.x, v.y - h01.y),
                                  f2bf2(v.z - h23.x, v.w - h23.y));
            *(uint2*)(smem + EI_H + pe[i] * 144 + pc[i] * 8) = hu;
            *(uint2*)(smem + EI_L + pe[i] * 144 + pc[i] * 8) = lu;
        }
        // node_f gather (prefetched indices) -> Act cols [0,64)
#pragma unroll
        for (int i = 0; i < 4; i++) {
            const float4 p = *(const float4*)(g_pq + (size_t)sidx[i] * 128 + pc[i] * 4);
            const float4 q = *(const float4*)(g_pq + (size_t)didx[i] * 128 + 64 + pc[i] * 4);
            float f0 = lrelu(p.x + q.x), f1 = lrelu(p.y + q.y);
            float f2 = lrelu(p.z + q.z), f3 = lrelu(p.w + q.w);
            uint2 hu = make_uint2(f2bf2(f0, f1), f2bf2(f2, f3));
            float2 h01 = bf2f(hu.x), h23 = bf2f(hu.y);
            uint2 lu = make_uint2(f2bf2(f0 - h01.x, f1 - h01.y),
                                  f2bf2(f2 - h23.x, f3 - h23.y));
            *(uint2*)(smem + ACT_H + pe[i] * 272 + pc[i] * 8) = hu;
            *(uint2*)(smem + ACT_L + pe[i] * 272 + pc[i] * 8) = lu;
        }

        // prefetch NEXT tile into the now-dead registers; latency hidden by stages
        {
            int en = e0 + gridDim.x * 64;
            if (en < EE) {
#pragma unroll
                for (int i = 0; i < 4; i++) {
                    eiv[i]  = *(const float4*)(EI + (size_t)(en + pe[i]) * 64 + pc[i] * 4);
                    sidx[i] = src[en + pe[i]];
                    didx[i] = dst[en + pe[i]];
                }
            }
        }
        __syncthreads();

        // stage1: edge_f = lrelu(EI @ Wee) -> Act cols [64,128), this warp's 32 cols
        {
            float c1[4][4];
#pragma unroll
            for (int nf = 0; nf < 4; nf++)
#pragma unroll
                for (int q = 0; q < 4; q++) c1[nf][q] = 0.f;
#pragma unroll
            for (int kk = 0; kk < 4; kk++) {
                uint32_t ah[4], al_[4];
                ldsm4(ah,  sb + EI_H + (r0 + rl) * 144 + ch16 + kk * 32);
                ldsm4(al_, sb + EI_L + (r0 + rl) * 144 + ch16 + kk * 32);
#pragma unroll
                for (int p = 0; p < 2; p++) {
                    uint32_t bh[4], bl_[4];
                    ldsm4t(bh,  sb + WEE_H + (kk * 16 + rl) * 144 + cg0 * 2 + p * 32 + ch16);
                    ldsm4t(bl_, sb + WEE_L + (kk * 16 + rl) * 144 + cg0 * 2 + p * 32 + ch16);
                    mma_bf16(c1[2 * p],     ah,  bh);
                    mma_bf16(c1[2 * p],     al_, bh);
                    mma_bf16(c1[2 * p],     ah,  bl_);
                    mma_bf16(c1[2 * p + 1], ah,  bh + 2);
                    mma_bf16(c1[2 * p + 1], al_, bh + 2);
                    mma_bf16(c1[2 * p + 1], ah,  bl_ + 2);
                }
            }
#pragma unroll
            for (int nf = 0; nf < 4; nf++) {
                int col = 64 + cg0 + nf * 8 + (lane & 3) * 2;
                float f0 = lrelu(c1[nf][0]), f1 = lrelu(c1[nf][1]);
                uint32_t h = f2bf2(f0, f1); float2 hh = bf2f(h);
                *(uint32_t*)(smem + ACT_H + ra * 272 + col * 2) = h;
                *(uint32_t*)(smem + ACT_L + ra * 272 + col * 2) = f2bf2(f0 - hh.x, f1 - hh.y);
                float f2 = lrelu(c1[nf][2]), f3 = lrelu(c1[nf][3]);
                uint32_t h2 = f2bf2(f2, f3); float2 hh2 = bf2f(h2);
                *(uint32_t*)(smem + ACT_H + rb * 272 + col * 2) = h2;
                *(uint32_t*)(smem + ACT_L + rb * 272 + col * 2) = f2bf2(f2 - hh2.x, f3 - hh2.y);
            }
        }
        __syncthreads();   // stage2 reads cols written by the other column-group warp

        // stage2: out = lrelu(Act @ Wf + EI), this warp's 32 cols
        {
            float c2[4][4];
#pragma unroll
            for (int nf = 0; nf < 4; nf++) {
                int col = cg0 + nf * 8 + (lane & 3) * 2;
                float2 ha = bf2f(*(uint32_t*)(smem + EI_H + ra * 144 + col * 2));
                float2 la = bf2f(*(uint32_t*)(smem + EI_L + ra * 144 + col * 2));
                float2 hb = bf2f(*(uint32_t*)(smem + EI_H + rb * 144 + col * 2));
                float2 lb = bf2f(*(uint32_t*)(smem + EI_L + rb * 144 + col * 2));
                c2[nf][0] = ha.x + la.x; c2[nf][1] = ha.y + la.y;
                c2[nf][2] = hb.x + lb.x; c2[nf][3] = hb.y + lb.y;
            }
#pragma unroll
            for (int kk = 0; kk < 8; kk++) {
                uint32_t ah[4], al_[4];
                ldsm4(ah,  sb + ACT_H + (r0 + rl) * 272 + ch16 + kk * 32);
                ldsm4(al_, sb + ACT_L + (r0 + rl) * 272 + ch16 + kk * 32);
#pragma unroll
                for (int p = 0; p < 2; p++) {
                    uint32_t bh[4], bl_[4];
                    ldsm4t(bh,  sb + WF_H + (kk * 16 + rl) * 144 + cg0 * 2 + p * 32 + ch16);
                    ldsm4t(bl_, sb + WF_L + (kk * 16 + rl) * 144 + cg0 * 2 + p * 32 + ch16);
                    mma_bf16(c2[2 * p],     ah,  bh);
                    mma_bf16(c2[2 * p],     al_, bh);
                    mma_bf16(c2[2 * p],     ah,  bl_);
                    mma_bf16(c2[2 * p + 1], ah,  bh + 2);
                    mma_bf16(c2[2 * p + 1], al_, bh + 2);
                    mma_bf16(c2[2 * p + 1], ah,  bl_ + 2);
                }
            }
#pragma unroll
            for (int nf = 0; nf < 4; nf++) {
                int col = cg0 + nf * 8 + (lane & 3) * 2;
                float o0 = lrelu(c2[nf][0]), o1 = lrelu(c2[nf][1]);
                float o2 = lrelu(c2[nf][2]), o3 = lrelu(c2[nf][3]);
                *(float2*)(out + (size_t)(e0 + ra) * 64 + col) = make_float2(o0, o1);
                *(float2*)(out + (size_t)(e0 + rb) * 64 + col) = make_float2(o2, o3);
                sls[nf * 2]     += o0 + o2; slq[nf * 2]     += o0 * o0 + o2 * o2;
                sls[nf * 2 + 1] += o1 + o3; slq[nf * 2 + 1] += o1 * o1 + o3 * o3;
            }
        }
    }

    __syncthreads();
#pragma unroll
    for (int t = 0; t < 8; t++) {
        int col = cg0 + (t >> 1) * 8 + (lane & 3) * 2 + (t & 1);
        atomicAdd(&sStat[col], sls[t]);
        atomicAdd(&sStat[64 + col], slq[t]);
    }
    __syncthreads();
    if (tid < 128) atomicAdd(&g_estat[tid], sStat[tid]);
}

// ---------------- side stream + events (created at load, outside checkpoints)
struct SideStream {
    cudaStream_t s = nullptr;
    cudaEvent_t fork = nullptr, mid = nullptr, join = nullptr, join2 = nullptr;
    SideStream() {
        cudaStreamCreateWithFlags(&s, cudaStreamNonBlocking);
        cudaEventCreateWithFlags(&fork, cudaEventDisableTiming);
        cudaEventCreateWithFlags(&mid,  cudaEventDisableTiming);
        cudaEventCreateWithFlags(&join, cudaEventDisableTiming);
        cudaEventCreateWithFlags(&join2, cudaEventDisableTiming);
    }
};
static SideStream g_ss;

// ---------------- launch --------------------------------------------------------
extern "C" void kernel_launch(void* const* d_in, const int* in_sizes, int n_in,
                              void* d_out, int out_size) {
    const float* node_in    = (const float*)d_in[0];
    const float* edge_in    = (const float*)d_in[1];
    const float* fc_w       = (const float*)d_in[2];
    const float* attn_l     = (const float*)d_in[3];
    const float* attn_r     = (const float*)d_in[4];
    const float* ae_w1      = (const float*)d_in[5];
    const float* ae_b1      = (const float*)d_in[6];
    const float* ae_w2      = (const float*)d_in[7];
    const float* ae_b2      = (const float*)d_in[8];
    const float* bn_n_g     = (const float*)d_in[9];
    const float* bn_n_b     = (const float*)d_in[10];
    const float* eu_node_w  = (const float*)d_in[11];
    const float* eu_edge_w  = (const float*)d_in[12];
    const float* eu_final_w = (const float*)d_in[13];
    const float* bn_e_g     = (const float*)d_in[14];
    const float* bn_e_b     = (const float*)d_in[15];
    const int*   src        = (const int*)d_in[16];
    const int*   dst        = (const int*)d_in[17];

    float* out      = (float*)d_out;
    float* node_out = out;                       // [N, 256]
    float* edge_out = out + (size_t)NN * 256;    // [E, 64]

    float *p_ft, *p_pq, *p_pqw;
    cudaGetSymbolAddress((void**)&p_ft,  g_ft);
    cudaGetSymbolAddress((void**)&p_pq,  g_pq);
    cudaGetSymbolAddress((void**)&p_pqw, g_pqw);
    __nv_bfloat16 *p_ah, *p_al, *p_bh, *p_bl, *p_bh2, *p_bl2;
    cudaGetSymbolAddress((void**)&p_ah, g_ah);
    cudaGetSymbolAddress((void**)&p_al, g_al);
    cudaGetSymbolAddress((void**)&p_bh, g_bh);
    cudaGetSymbolAddress((void**)&p_bl, g_bl);
    cudaGetSymbolAddress((void**)&p_bh2, g_bh2);
    cudaGetSymbolAddress((void**)&p_bl2, g_bl2);

    const int GM_SMEM = 2 * 37888;
    cudaFuncSetAttribute(gemm_mma_k, cudaFuncAttributeMaxDynamicSharedMemorySize, GM_SMEM);
    cudaFuncSetAttribute(edge_final6_k, cudaFuncAttributeMaxDynamicSharedMemorySize, EF5_SMEM);

    cudaStream_t sB = g_ss.s;

    // fork: side stream handles CSR build + edge_attn, then pqw prep
    cudaEventRecord(g_ss.fork, 0);
    cudaStreamWaitEvent(sB, g_ss.fork, 0);

    // ---- side stream: CSR chain only (pqw prep deferred past edge_attn) ----
    zero_all_k<<<196, 256, 0, sB>>>();
    count_edges_k<<<(EE + 255) / 256, 256, 0, sB>>>(dst);
    scan_block_k<<<NB_SCAN, 1024, 0, sB>>>();
    finish_scan2_k<<<NB_SCAN, 1024, 0, sB>>>();
    scatter_k<<<(EE + 255) / 256, 256, 0, sB>>>(src, dst);

    // ---- main stream: node features ----
    conv_b_k<<<256, 256>>>(fc_w, p_bh, p_bl, 256 * 256);
    build_fla_k<<<16, 256>>>(fc_w, attn_l, attn_r);
    conv_attn_k<<<6250, 256>>>(node_in);
    cudaEventRecord(g_ss.mid, 0);                      // a1/a2 + splits ready
    gemm_mma_k<<<dim3(2, 391), 256, GM_SMEM>>>(p_ah, p_al, p_bh, p_bl, p_ft, NN, 256);

    // ---- side stream: edge attention first (join-critical), then pqw prep ----
    cudaStreamWaitEvent(sB, g_ss.mid, 0);
    edge_attn2_k<<<592, 256, 0, sB>>>(edge_in, ae_w1, ae_b1, ae_w2, ae_b2, src, dst);
    cudaEventRecord(g_ss.join, sB);                    // gates node_agg
    build_pqw_k<<<128, 256, 0, sB>>>(eu_node_w);
    conv_b_k<<<128, 256, 0, sB>>>(p_pqw, p_bh2, p_bl2, 256 * 128);
    cudaEventRecord(g_ss.join2, sB);                   // gates gemm_pq

    // ---- join, then the dependent tail on main stream ----
    cudaStreamWaitEvent(0, g_ss.join, 0);
    node_agg_k<<<1184, 256>>>(node_in, node_out);
    finalize_node_k<<<1, 256>>>(bn_n_g, bn_n_b);
    conv_abn_k<<<25000, 256>>>(node_out);
    cudaStreamWaitEvent(0, g_ss.join2, 0);
    gemm_mma_k<<<dim3(1, 391), 256, GM_SMEM>>>(p_ah, p_al, p_bh2, p_bl2, p_pq, NN, 128);

    edge_final6_k<<<296, 256, EF5_SMEM>>>(edge_in, src, dst, eu_edge_w, eu_final_w, edge_out);
    finalize_edge_k<<<1, 64>>>(bn_e_g, bn_e_b);
    apply_bn_edge_k<<<4096, 256>>>(edge_out);
}